// round 7
// baseline (speedup 1.0000x reference)
#include <cuda_runtime.h>
#include <math.h>

// ---------------------------------------------------------------------------
// Problem constants (from setup_inputs)
// ---------------------------------------------------------------------------
#define B_    16
#define N1_   4096
#define N2_   1024
#define KNB   32
#define CIN0  67            // 64 feature channels + 3 xyz
#define CPAD  68            // padded to multiple of 4
#define C0    64
#define C1O   64
#define C2    128
#define M_    (B_ * N2_ * KNB)     // 524288 rows (b, n2, k)
#define NB01  (M_ / 256)           // 2048 blocks for layers 0/1
#define NB2   (M_ / 128)           // 4096 blocks for layer 2
#define CNT_  524288.0f
#define EPS_  1e-5f

// ---------------------------------------------------------------------------
// Scratch (device globals: no allocation allowed)
// ---------------------------------------------------------------------------
__device__ float g_xallT[B_ * N1_ * CPAD];          // [B][N1][68]  feat+xyz, channels-last
__device__ float g_oxyz [B_ * N2_ * 4];             // [B][N2][4]   query xyz
__device__ float g_y0[(size_t)M_ * C0];             // layer0 raw conv out, [row][64]
__device__ float g_y1[(size_t)M_ * C1O];            // layer1 raw conv out
__device__ float g_part0[2 * NB01 * C0];            // per-block partial sum / sumsq
__device__ float g_part1[2 * NB01 * C1O];
__device__ float g_part2[2 * NB2  * C2];
__device__ float g_scale0[C0],  g_shift0[C0];
__device__ float g_scale1[C1O], g_shift1[C1O];
__device__ float g_scale2[C2],  g_shift2[C2];
__device__ float g_max2[B_ * N2_ * C2];             // [B][N2][128] max over K of raw y2
__device__ float g_min2[B_ * N2_ * C2];             // min (for scale<0 case)

// ---------------------------------------------------------------------------
// Kernel 0a: transpose in_feature [B,64,N1] (+ in_xyz [B,3,N1]) -> g_xallT [B,N1,68]
// ---------------------------------------------------------------------------
__global__ void transpose_kernel(const float* __restrict__ in_feature,
                                 const float* __restrict__ in_xyz) {
    __shared__ float tile[CPAD][33];
    int b  = blockIdx.y;
    int n0 = blockIdx.x * 32;
    int tx = threadIdx.x;      // 32
    int ty = threadIdx.y;      // 8
    for (int c = ty; c < CPAD; c += 8) {
        float v;
        if (c < 64)      v = in_feature[((size_t)b * 64 + c) * N1_ + n0 + tx];
        else if (c < 67) v = in_xyz[((size_t)b * 3 + (c - 64)) * N1_ + n0 + tx];
        else             v = 0.0f;
        tile[c][tx] = v;
    }
    __syncthreads();
    int tid = ty * 32 + tx;
    for (int e = tid; e < 32 * CPAD; e += 256) {
        int nl = e / CPAD;
        int c  = e % CPAD;
        g_xallT[((size_t)(b * N1_ + n0 + nl)) * CPAD + c] = tile[c][nl];
    }
}

// Kernel 0b: out_xyz [B,3,N2] -> g_oxyz [B,N2,4]
__global__ void oxyz_kernel(const float* __restrict__ out_xyz) {
    int i = blockIdx.x * 256 + threadIdx.x;
    if (i >= B_ * N2_) return;
    int b = i / N2_, n2 = i % N2_;
    float x = out_xyz[(b * 3 + 0) * N2_ + n2];
    float y = out_xyz[(b * 3 + 1) * N2_ + n2];
    float z = out_xyz[(b * 3 + 2) * N2_ + n2];
    g_oxyz[i * 4 + 0] = x;
    g_oxyz[i * 4 + 1] = y;
    g_oxyz[i * 4 + 2] = z;
    g_oxyz[i * 4 + 3] = 0.0f;
}

// ---------------------------------------------------------------------------
// Kernel 1: gather + GEMM0 (Kc=67 -> 64) + per-block BN stats partials
// Tile: 256 rows x 64 cols, 256 threads, 8x8 per thread.
// smem: Xsh[68][256] + Wsh[68][64]  (dynamic, 87040 B)
// ---------------------------------------------------------------------------
__global__ __launch_bounds__(256) void gemm0_kernel(const int* __restrict__ nbr,
                                                    const float* __restrict__ W0) {
    extern __shared__ float sm[];
    float* Xsh = sm;                    // [CPAD][256]
    float* Wsh = sm + CPAD * 256;       // [CPAD][64]
    int tid = threadIdx.x;

    // Load W0 [64][67] transposed into Wsh[ci][co]
    for (int e = tid; e < C0 * CIN0; e += 256) {
        int co = e / CIN0, ci = e % CIN0;
        Wsh[ci * C0 + co] = W0[e];
    }
    if (tid < C0) Wsh[67 * C0 + tid] = 0.0f;

    // Gather one row per thread: X[row][c] for c in [0,68)
    int row0 = blockIdx.x * 256;
    {
        int R   = row0 + tid;
        int b   = R >> 15;              // /(N2*K) = /32768
        int n2  = (R >> 5) & (N2_ - 1);
        int idx = nbr[R];
        const float4* src = (const float4*)(g_xallT + (size_t)(b * N1_ + idx) * CPAD);
        const float4  oz  = *(const float4*)(g_oxyz + (size_t)(b * N2_ + n2) * 4);
#pragma unroll
        for (int q = 0; q < 17; q++) {
            float4 v = src[q];
            if (q == 16) { v.x -= oz.x; v.y -= oz.y; v.z -= oz.z; v.w = 0.0f; }
            Xsh[(q * 4 + 0) * 256 + tid] = v.x;
            Xsh[(q * 4 + 1) * 256 + tid] = v.y;
            Xsh[(q * 4 + 2) * 256 + tid] = v.z;
            Xsh[(q * 4 + 3) * 256 + tid] = v.w;
        }
    }
    __syncthreads();

    int cg = tid & 7, rg = tid >> 3;
    float acc[8][8];
#pragma unroll
    for (int i = 0; i < 8; i++)
#pragma unroll
        for (int j = 0; j < 8; j++) acc[i][j] = 0.0f;

    const float* Xp = Xsh + rg * 8;
    const float* Wp = Wsh + cg * 8;
#pragma unroll 4
    for (int kk = 0; kk < CIN0; kk++) {
        float a[8], bb[8];
        float4 t;
        t = *(const float4*)(Xp + kk * 256);     a[0]=t.x; a[1]=t.y; a[2]=t.z; a[3]=t.w;
        t = *(const float4*)(Xp + kk * 256 + 4); a[4]=t.x; a[5]=t.y; a[6]=t.z; a[7]=t.w;
        t = *(const float4*)(Wp + kk * C0);      bb[0]=t.x; bb[1]=t.y; bb[2]=t.z; bb[3]=t.w;
        t = *(const float4*)(Wp + kk * C0 + 4);  bb[4]=t.x; bb[5]=t.y; bb[6]=t.z; bb[7]=t.w;
#pragma unroll
        for (int i = 0; i < 8; i++)
#pragma unroll
            for (int j = 0; j < 8; j++) acc[i][j] = fmaf(a[i], bb[j], acc[i][j]);
    }

    // Write y0
#pragma unroll
    for (int i = 0; i < 8; i++) {
        float* dst = g_y0 + (size_t)(row0 + rg * 8 + i) * C0 + cg * 8;
        float4 o0 = {acc[i][0], acc[i][1], acc[i][2], acc[i][3]};
        float4 o1 = {acc[i][4], acc[i][5], acc[i][6], acc[i][7]};
        *(float4*)dst = o0; *(float4*)(dst + 4) = o1;
    }

    // Block-local BN stats (sum / sumsq per channel over 256 rows)
    __syncthreads();
    float* redS = Xsh;
    float* redQ = Xsh + 32 * C0;
#pragma unroll
    for (int j = 0; j < 8; j++) {
        float s = 0.0f, q = 0.0f;
#pragma unroll
        for (int i = 0; i < 8; i++) { float v = acc[i][j]; s += v; q += v * v; }
        redS[rg * C0 + cg * 8 + j] = s;
        redQ[rg * C0 + cg * 8 + j] = q;
    }
    __syncthreads();
    if (tid < 2 * C0) {
        int which = tid >> 6, c = tid & 63;
        const float* src = which ? redQ : redS;
        float s = 0.0f;
        for (int g = 0; g < 32; g++) s += src[g * C0 + c];
        g_part0[(size_t)which * NB01 * C0 + (size_t)blockIdx.x * C0 + c] = s;
    }
}

// ---------------------------------------------------------------------------
// Kernel 2: GEMM1 (64->64), input = relu(scale0*y0+shift0) applied on load
// ---------------------------------------------------------------------------
__global__ __launch_bounds__(256) void gemm_mid_kernel(const float* __restrict__ W1) {
    extern __shared__ float sm[];
    float* Xsh = sm;                       // [64][256]
    float* Wsh = sm + 64 * 256;            // [64][64]
    float* scb = Wsh + 64 * 64;            // [64]
    float* shb = scb + 64;                 // [64]
    int tid = threadIdx.x;

    for (int e = tid; e < 64 * 64; e += 256) {
        int co = e >> 6, ci = e & 63;
        Wsh[ci * 64 + co] = W1[e];
    }
    if (tid < C0) { scb[tid] = g_scale0[tid]; shb[tid] = g_shift0[tid]; }
    __syncthreads();

    int row0 = blockIdx.x * 256;
    {
        const float4* src = (const float4*)(g_y0 + (size_t)(row0 + tid) * C0);
#pragma unroll
        for (int q = 0; q < 16; q++) {
            float4 v = src[q];
            int c = q * 4;
            v.x = fmaxf(0.0f, fmaf(v.x, scb[c + 0], shb[c + 0]));
            v.y = fmaxf(0.0f, fmaf(v.y, scb[c + 1], shb[c + 1]));
            v.z = fmaxf(0.0f, fmaf(v.z, scb[c + 2], shb[c + 2]));
            v.w = fmaxf(0.0f, fmaf(v.w, scb[c + 3], shb[c + 3]));
            Xsh[(c + 0) * 256 + tid] = v.x;
            Xsh[(c + 1) * 256 + tid] = v.y;
            Xsh[(c + 2) * 256 + tid] = v.z;
            Xsh[(c + 3) * 256 + tid] = v.w;
        }
    }
    __syncthreads();

    int cg = tid & 7, rg = tid >> 3;
    float acc[8][8];
#pragma unroll
    for (int i = 0; i < 8; i++)
#pragma unroll
        for (int j = 0; j < 8; j++) acc[i][j] = 0.0f;

    const float* Xp = Xsh + rg * 8;
    const float* Wp = Wsh + cg * 8;
#pragma unroll 4
    for (int kk = 0; kk < 64; kk++) {
        float a[8], bb[8];
        float4 t;
        t = *(const float4*)(Xp + kk * 256);     a[0]=t.x; a[1]=t.y; a[2]=t.z; a[3]=t.w;
        t = *(const float4*)(Xp + kk * 256 + 4); a[4]=t.x; a[5]=t.y; a[6]=t.z; a[7]=t.w;
        t = *(const float4*)(Wp + kk * 64);      bb[0]=t.x; bb[1]=t.y; bb[2]=t.z; bb[3]=t.w;
        t = *(const float4*)(Wp + kk * 64 + 4);  bb[4]=t.x; bb[5]=t.y; bb[6]=t.z; bb[7]=t.w;
#pragma unroll
        for (int i = 0; i < 8; i++)
#pragma unroll
            for (int j = 0; j < 8; j++) acc[i][j] = fmaf(a[i], bb[j], acc[i][j]);
    }

#pragma unroll
    for (int i = 0; i < 8; i++) {
        float* dst = g_y1 + (size_t)(row0 + rg * 8 + i) * C1O + cg * 8;
        float4 o0 = {acc[i][0], acc[i][1], acc[i][2], acc[i][3]};
        float4 o1 = {acc[i][4], acc[i][5], acc[i][6], acc[i][7]};
        *(float4*)dst = o0; *(float4*)(dst + 4) = o1;
    }

    __syncthreads();
    float* redS = Xsh;
    float* redQ = Xsh + 32 * C1O;
#pragma unroll
    for (int j = 0; j < 8; j++) {
        float s = 0.0f, q = 0.0f;
#pragma unroll
        for (int i = 0; i < 8; i++) { float v = acc[i][j]; s += v; q += v * v; }
        redS[rg * C1O + cg * 8 + j] = s;
        redQ[rg * C1O + cg * 8 + j] = q;
    }
    __syncthreads();
    if (tid < 2 * C1O) {
        int which = tid >> 6, c = tid & 63;
        const float* src = which ? redQ : redS;
        float s = 0.0f;
        for (int g = 0; g < 32; g++) s += src[g * C1O + c];
        g_part1[(size_t)which * NB01 * C1O + (size_t)blockIdx.x * C1O + c] = s;
    }
}

// ---------------------------------------------------------------------------
// Kernel 3: GEMM2 (64->128) + BN stats + fused max/min over K (no y2 store)
// Tile: 128 rows x 128 cols, 256 threads, 8x8 per thread.
// ---------------------------------------------------------------------------
__global__ __launch_bounds__(256) void gemm_last_kernel(const float* __restrict__ W2) {
    extern __shared__ float sm[];
    float* Xsh = sm;                        // [64][128]
    float* Wsh = sm + 64 * 128;             // [64][128]
    float* scb = Wsh + 64 * 128;            // [64]
    float* shb = scb + 64;                  // [64]
    int tid = threadIdx.x;

    for (int e = tid; e < C2 * 64; e += 256) {
        int co = e >> 6, ci = e & 63;
        Wsh[ci * C2 + co] = W2[e];
    }
    if (tid < C1O) { scb[tid] = g_scale1[tid]; shb[tid] = g_shift1[tid]; }
    __syncthreads();

    int row0 = blockIdx.x * 128;
    {
        int r = tid >> 1, half = tid & 1;
        const float4* src = (const float4*)(g_y1 + (size_t)(row0 + r) * C1O + half * 32);
#pragma unroll
        for (int q = 0; q < 8; q++) {
            float4 v = src[q];
            int c = half * 32 + q * 4;
            v.x = fmaxf(0.0f, fmaf(v.x, scb[c + 0], shb[c + 0]));
            v.y = fmaxf(0.0f, fmaf(v.y, scb[c + 1], shb[c + 1]));
            v.z = fmaxf(0.0f, fmaf(v.z, scb[c + 2], shb[c + 2]));
            v.w = fmaxf(0.0f, fmaf(v.w, scb[c + 3], shb[c + 3]));
            Xsh[(c + 0) * 128 + r] = v.x;
            Xsh[(c + 1) * 128 + r] = v.y;
            Xsh[(c + 2) * 128 + r] = v.z;
            Xsh[(c + 3) * 128 + r] = v.w;
        }
    }
    __syncthreads();

    int cg = tid & 15, rg = tid >> 4;
    float acc[8][8];
#pragma unroll
    for (int i = 0; i < 8; i++)
#pragma unroll
        for (int j = 0; j < 8; j++) acc[i][j] = 0.0f;

    const float* Xp = Xsh + rg * 8;
    const float* Wp = Wsh + cg * 8;
#pragma unroll 4
    for (int kk = 0; kk < 64; kk++) {
        float a[8], bb[8];
        float4 t;
        t = *(const float4*)(Xp + kk * 128);     a[0]=t.x; a[1]=t.y; a[2]=t.z; a[3]=t.w;
        t = *(const float4*)(Xp + kk * 128 + 4); a[4]=t.x; a[5]=t.y; a[6]=t.z; a[7]=t.w;
        t = *(const float4*)(Wp + kk * C2);      bb[0]=t.x; bb[1]=t.y; bb[2]=t.z; bb[3]=t.w;
        t = *(const float4*)(Wp + kk * C2 + 4);  bb[4]=t.x; bb[5]=t.y; bb[6]=t.z; bb[7]=t.w;
#pragma unroll
        for (int i = 0; i < 8; i++)
#pragma unroll
            for (int j = 0; j < 8; j++) acc[i][j] = fmaf(a[i], bb[j], acc[i][j]);
    }

    // --- Phase A: BN stats partials ---
    __syncthreads();
    float* redS = Xsh;                 // [16][128]
    float* redQ = Xsh + 16 * C2;       // [16][128]
#pragma unroll
    for (int j = 0; j < 8; j++) {
        float s = 0.0f, q = 0.0f;
#pragma unroll
        for (int i = 0; i < 8; i++) { float v = acc[i][j]; s += v; q += v * v; }
        redS[rg * C2 + cg * 8 + j] = s;
        redQ[rg * C2 + cg * 8 + j] = q;
    }
    __syncthreads();
    {
        int which = tid >> 7, c = tid & 127;
        const float* src = which ? redQ : redS;
        float s = 0.0f;
        for (int g = 0; g < 16; g++) s += src[g * C2 + c];
        g_part2[(size_t)which * NB2 * C2 + (size_t)blockIdx.x * C2 + c] = s;
    }

    // --- Phase B: max/min over K (each thread's 8 rows lie inside one K-group) ---
    __syncthreads();
    float* redM = Xsh;
    float* redN = Xsh + 16 * C2;
#pragma unroll
    for (int j = 0; j < 8; j++) {
        float mx = acc[0][j], mn = acc[0][j];
#pragma unroll
        for (int i = 1; i < 8; i++) { mx = fmaxf(mx, acc[i][j]); mn = fminf(mn, acc[i][j]); }
        redM[rg * C2 + cg * 8 + j] = mx;
        redN[rg * C2 + cg * 8 + j] = mn;
    }
    __syncthreads();
    // 4 K-groups of 32 rows per block: combine rg {4g..4g+3}
    for (int e = tid; e < 4 * C2; e += 256) {
        int g = e >> 7, c = e & 127;
        float mx = redM[(4 * g + 0) * C2 + c];
        float mn = redN[(4 * g + 0) * C2 + c];
#pragma unroll
        for (int t = 1; t < 4; t++) {
            mx = fmaxf(mx, redM[(4 * g + t) * C2 + c]);
            mn = fminf(mn, redN[(4 * g + t) * C2 + c]);
        }
        int b  = row0 >> 15;
        int n2 = ((row0 >> 5) & (N2_ - 1)) + g;
        size_t o = (size_t)(b * N2_ + n2) * C2 + c;
        g_max2[o] = mx;
        g_min2[o] = mn;
    }
}

// ---------------------------------------------------------------------------
// Stats finalize: reduce per-block partials -> scale/shift (deterministic)
// grid.x = C, 256 threads
// ---------------------------------------------------------------------------
__global__ void stats_kernel(int layer, const float* __restrict__ gamma,
                             const float* __restrict__ beta) {
    const float* part; int nb, C; float* scale; float* shift;
    if (layer == 0)      { part = g_part0; nb = NB01; C = C0;  scale = g_scale0; shift = g_shift0; }
    else if (layer == 1) { part = g_part1; nb = NB01; C = C1O; scale = g_scale1; shift = g_shift1; }
    else                 { part = g_part2; nb = NB2;  C = C2;  scale = g_scale2; shift = g_shift2; }

    __shared__ float shs[256], shq[256];
    int c = blockIdx.x;
    int tid = threadIdx.x;
    float s = 0.0f, q = 0.0f;
    for (int i = tid; i < nb; i += 256) {
        s += part[(size_t)i * C + c];
        q += part[(size_t)(nb + i) * C + c];
    }
    shs[tid] = s; shq[tid] = q;
    __syncthreads();
    for (int off = 128; off > 0; off >>= 1) {
        if (tid < off) { shs[tid] += shs[tid + off]; shq[tid] += shq[tid + off]; }
        __syncthreads();
    }
    if (tid == 0) {
        float mean = shs[0] / CNT_;
        float var  = shq[0] / CNT_ - mean * mean;
        float sc   = gamma[c] * rsqrtf(var + EPS_);
        scale[c] = sc;
        shift[c] = beta[c] - mean * sc;
    }
}

// ---------------------------------------------------------------------------
// Final: out[b][c][n2] = relu(scale2*val + shift2), val = max (or min if scale<0)
// ---------------------------------------------------------------------------
__global__ void final_kernel(float* __restrict__ out) {
    int o = blockIdx.x * 256 + threadIdx.x;
    if (o >= B_ * C2 * N2_) return;
    int n2 = o & (N2_ - 1);
    int c  = (o >> 10) & (C2 - 1);
    int b  = o >> 17;
    float sc = g_scale2[c], sh = g_shift2[c];
    size_t mi = (size_t)(b * N2_ + n2) * C2 + c;
    float v = (sc >= 0.0f) ? g_max2[mi] : g_min2[mi];
    out[o] = fmaxf(0.0f, fmaf(sc, v, sh));
}

// ---------------------------------------------------------------------------
// Launcher
// ---------------------------------------------------------------------------
extern "C" void kernel_launch(void* const* d_in, const int* in_sizes, int n_in,
                              void* d_out, int out_size) {
    const float* in_xyz     = (const float*)d_in[0];
    const float* out_xyz    = (const float*)d_in[1];
    const float* in_feature = (const float*)d_in[2];
    const int*   nbr        = (const int*)  d_in[3];
    const float* W0 = (const float*)d_in[4];
    const float* g0 = (const float*)d_in[5];
    const float* b0 = (const float*)d_in[6];
    const float* W1 = (const float*)d_in[7];
    const float* g1 = (const float*)d_in[8];
    const float* b1 = (const float*)d_in[9];
    const float* W2 = (const float*)d_in[10];
    const float* g2 = (const float*)d_in[11];
    const float* b2 = (const float*)d_in[12];
    float* out = (float*)d_out;

    const int SM0B = (CPAD * 256 + CPAD * 64) * 4;            // 87040
    const int SM1B = (64 * 256 + 64 * 64 + 128) * 4;          // 82432
    const int SM2B = (64 * 128 + 64 * 128 + 128) * 4;         // 66048

    cudaFuncSetAttribute(gemm0_kernel,    cudaFuncAttributeMaxDynamicSharedMemorySize, SM0B);
    cudaFuncSetAttribute(gemm_mid_kernel, cudaFuncAttributeMaxDynamicSharedMemorySize, SM1B);
    cudaFuncSetAttribute(gemm_last_kernel,cudaFuncAttributeMaxDynamicSharedMemorySize, SM2B);

    transpose_kernel<<<dim3(N1_ / 32, B_), dim3(32, 8)>>>(in_feature, in_xyz);
    oxyz_kernel<<<(B_ * N2_ + 255) / 256, 256>>>(out_xyz);

    gemm0_kernel<<<NB01, 256, SM0B>>>(nbr, W0);
    stats_kernel<<<C0, 256>>>(0, g0, b0);

    gemm_mid_kernel<<<NB01, 256, SM1B>>>(W1);
    stats_kernel<<<C1O, 256>>>(1, g1, b1);

    gemm_last_kernel<<<NB2, 256, SM2B>>>(W2);
    stats_kernel<<<C2, 256>>>(2, g2, b2);

    final_kernel<<<(B_ * C2 * N2_ + 255) / 256, 256>>>(out);
}

// round 8
// speedup vs baseline: 1.6158x; 1.6158x over previous
#include <cuda_runtime.h>
#include <math.h>

// ---------------------------------------------------------------------------
// Problem constants
// ---------------------------------------------------------------------------
#define B_    16
#define N1_   4096
#define N2_   1024
#define KNB   32
#define CIN0  67
#define CPAD  68
#define C0    64
#define C1O   64
#define C2    128
#define M_    (B_ * N2_ * KNB)     // 524288
#define NB01  (M_ / 256)           // 2048
#define NB2   (M_ / 128)           // 4096
#define CNT_  524288.0f
#define EPS_  1e-5f

typedef unsigned long long u64;

// packed fp32x2 helpers (Blackwell FFMA2 path — ptxas never auto-fuses)
__device__ __forceinline__ void fma2(u64& d, u64 a, u64 b) {
    asm("fma.rn.f32x2 %0, %1, %2, %0;" : "+l"(d) : "l"(a), "l"(b));
}
__device__ __forceinline__ u64 rep2(float x) {
    u64 r; asm("mov.b64 %0, {%1, %1};" : "=l"(r) : "f"(x)); return r;
}
__device__ __forceinline__ float2 unp2(u64 v) {
    float2 f; asm("mov.b64 {%0, %1}, %2;" : "=f"(f.x), "=f"(f.y) : "l"(v)); return f;
}

// ---------------------------------------------------------------------------
// Scratch
// ---------------------------------------------------------------------------
__device__ float g_xallT[B_ * N1_ * CPAD];
__device__ float g_oxyz [B_ * N2_ * 4];
__device__ float g_y0[(size_t)M_ * C0];
__device__ float g_y1[(size_t)M_ * C1O];
__device__ float g_part0[2 * NB01 * C0];
__device__ float g_part1[2 * NB01 * C1O];
__device__ float g_part2[2 * NB2  * C2];
__device__ float g_scale0[C0],  g_shift0[C0];
__device__ float g_scale1[C1O], g_shift1[C1O];
__device__ float g_scale2[C2],  g_shift2[C2];
__device__ float g_max2[B_ * N2_ * C2];
__device__ float g_min2[B_ * N2_ * C2];

// ---------------------------------------------------------------------------
// Kernel 0a: transpose feat+xyz -> [B][N1][68]
// ---------------------------------------------------------------------------
__global__ void transpose_kernel(const float* __restrict__ in_feature,
                                 const float* __restrict__ in_xyz) {
    __shared__ float tile[CPAD][33];
    int b  = blockIdx.y;
    int n0 = blockIdx.x * 32;
    int tx = threadIdx.x;
    int ty = threadIdx.y;
    for (int c = ty; c < CPAD; c += 8) {
        float v;
        if (c < 64)      v = in_feature[((size_t)b * 64 + c) * N1_ + n0 + tx];
        else if (c < 67) v = in_xyz[((size_t)b * 3 + (c - 64)) * N1_ + n0 + tx];
        else             v = 0.0f;
        tile[c][tx] = v;
    }
    __syncthreads();
    int tid = ty * 32 + tx;
    for (int e = tid; e < 32 * CPAD; e += 256) {
        int nl = e / CPAD;
        int c  = e % CPAD;
        g_xallT[((size_t)(b * N1_ + n0 + nl)) * CPAD + c] = tile[c][nl];
    }
}

__global__ void oxyz_kernel(const float* __restrict__ out_xyz) {
    int i = blockIdx.x * 256 + threadIdx.x;
    if (i >= B_ * N2_) return;
    int b = i / N2_, n2 = i % N2_;
    g_oxyz[i * 4 + 0] = out_xyz[(b * 3 + 0) * N2_ + n2];
    g_oxyz[i * 4 + 1] = out_xyz[(b * 3 + 1) * N2_ + n2];
    g_oxyz[i * 4 + 2] = out_xyz[(b * 3 + 2) * N2_ + n2];
    g_oxyz[i * 4 + 3] = 0.0f;
}

// ---------------------------------------------------------------------------
// Kernel 1: gather + GEMM0 (68 -> 64, padded K) + BN stat partials
// ---------------------------------------------------------------------------
__global__ __launch_bounds__(256, 2) void gemm0_kernel(const int* __restrict__ nbr,
                                                       const float* __restrict__ W0) {
    extern __shared__ float sm[];
    float* Xsh = sm;                    // [CPAD][256]
    float* Wsh = sm + CPAD * 256;       // [CPAD][64]
    int tid = threadIdx.x;

    for (int e = tid; e < C0 * CIN0; e += 256) {
        int co = e / CIN0, ci = e % CIN0;
        Wsh[ci * C0 + co] = W0[e];
    }
    if (tid < C0) Wsh[67 * C0 + tid] = 0.0f;

    int row0 = blockIdx.x * 256;
    {
        int R   = row0 + tid;
        int b   = R >> 15;
        int n2  = (R >> 5) & (N2_ - 1);
        int idx = nbr[R];
        const float4* src = (const float4*)(g_xallT + (size_t)(b * N1_ + idx) * CPAD);
        const float4  oz  = *(const float4*)(g_oxyz + (size_t)(b * N2_ + n2) * 4);
#pragma unroll
        for (int q = 0; q < 17; q++) {
            float4 v = src[q];
            if (q == 16) { v.x -= oz.x; v.y -= oz.y; v.z -= oz.z; v.w = 0.0f; }
            Xsh[(q * 4 + 0) * 256 + tid] = v.x;
            Xsh[(q * 4 + 1) * 256 + tid] = v.y;
            Xsh[(q * 4 + 2) * 256 + tid] = v.z;
            Xsh[(q * 4 + 3) * 256 + tid] = v.w;
        }
    }
    __syncthreads();

    int cg = tid & 7, rg = tid >> 3;
    u64 acc[8][4];
#pragma unroll
    for (int i = 0; i < 8; i++)
#pragma unroll
        for (int j = 0; j < 4; j++) acc[i][j] = 0ull;

    const float* Xp = Xsh + rg * 8;
    const float* Wp = Wsh + cg * 8;
#pragma unroll 4
    for (int kk = 0; kk < CPAD; kk++) {
        float4 ta0 = *(const float4*)(Xp + kk * 256);
        float4 ta1 = *(const float4*)(Xp + kk * 256 + 4);
        ulonglong2 tb0 = *(const ulonglong2*)(Wp + kk * C0);
        ulonglong2 tb1 = *(const ulonglong2*)(Wp + kk * C0 + 4);
        u64 b2[4] = {tb0.x, tb0.y, tb1.x, tb1.y};
        float a[8] = {ta0.x, ta0.y, ta0.z, ta0.w, ta1.x, ta1.y, ta1.z, ta1.w};
#pragma unroll
        for (int i = 0; i < 8; i++) {
            u64 ar = rep2(a[i]);
#pragma unroll
            for (int j = 0; j < 4; j++) fma2(acc[i][j], ar, b2[j]);
        }
    }

#pragma unroll
    for (int i = 0; i < 8; i++) {
        ulonglong2* dst = (ulonglong2*)(g_y0 + (size_t)(row0 + rg * 8 + i) * C0 + cg * 8);
        dst[0] = make_ulonglong2(acc[i][0], acc[i][1]);
        dst[1] = make_ulonglong2(acc[i][2], acc[i][3]);
    }

    __syncthreads();
    float* redS = Xsh;
    float* redQ = Xsh + 32 * C0;
#pragma unroll
    for (int jp = 0; jp < 4; jp++) {
        float sx = 0.f, sy = 0.f, qx = 0.f, qy = 0.f;
#pragma unroll
        for (int i = 0; i < 8; i++) {
            float2 v = unp2(acc[i][jp]);
            sx += v.x; sy += v.y; qx += v.x * v.x; qy += v.y * v.y;
        }
        redS[rg * C0 + cg * 8 + 2 * jp]     = sx;
        redS[rg * C0 + cg * 8 + 2 * jp + 1] = sy;
        redQ[rg * C0 + cg * 8 + 2 * jp]     = qx;
        redQ[rg * C0 + cg * 8 + 2 * jp + 1] = qy;
    }
    __syncthreads();
    if (tid < 2 * C0) {
        int which = tid >> 6, c = tid & 63;
        const float* src = which ? redQ : redS;
        float s = 0.0f;
        for (int g = 0; g < 32; g++) s += src[g * C0 + c];
        g_part0[(size_t)which * NB01 * C0 + (size_t)blockIdx.x * C0 + c] = s;
    }
}

// ---------------------------------------------------------------------------
// Kernel 2: GEMM1 (64->64), BN0+ReLU fused on load
// ---------------------------------------------------------------------------
__global__ __launch_bounds__(256, 2) void gemm_mid_kernel(const float* __restrict__ W1) {
    extern __shared__ float sm[];
    float* Xsh = sm;                       // [64][256]
    float* Wsh = sm + 64 * 256;            // [64][64]
    float* scb = Wsh + 64 * 64;
    float* shb = scb + 64;
    int tid = threadIdx.x;

    for (int e = tid; e < 64 * 64; e += 256) {
        int co = e >> 6, ci = e & 63;
        Wsh[ci * 64 + co] = W1[e];
    }
    if (tid < C0) { scb[tid] = g_scale0[tid]; shb[tid] = g_shift0[tid]; }
    __syncthreads();

    int row0 = blockIdx.x * 256;
    {
        const float4* src = (const float4*)(g_y0 + (size_t)(row0 + tid) * C0);
#pragma unroll
        for (int q = 0; q < 16; q++) {
            float4 v = src[q];
            int c = q * 4;
            v.x = fmaxf(0.0f, fmaf(v.x, scb[c + 0], shb[c + 0]));
            v.y = fmaxf(0.0f, fmaf(v.y, scb[c + 1], shb[c + 1]));
            v.z = fmaxf(0.0f, fmaf(v.z, scb[c + 2], shb[c + 2]));
            v.w = fmaxf(0.0f, fmaf(v.w, scb[c + 3], shb[c + 3]));
            Xsh[(c + 0) * 256 + tid] = v.x;
            Xsh[(c + 1) * 256 + tid] = v.y;
            Xsh[(c + 2) * 256 + tid] = v.z;
            Xsh[(c + 3) * 256 + tid] = v.w;
        }
    }
    __syncthreads();

    int cg = tid & 7, rg = tid >> 3;
    u64 acc[8][4];
#pragma unroll
    for (int i = 0; i < 8; i++)
#pragma unroll
        for (int j = 0; j < 4; j++) acc[i][j] = 0ull;

    const float* Xp = Xsh + rg * 8;
    const float* Wp = Wsh + cg * 8;
#pragma unroll 4
    for (int kk = 0; kk < 64; kk++) {
        float4 ta0 = *(const float4*)(Xp + kk * 256);
        float4 ta1 = *(const float4*)(Xp + kk * 256 + 4);
        ulonglong2 tb0 = *(const ulonglong2*)(Wp + kk * 64);
        ulonglong2 tb1 = *(const ulonglong2*)(Wp + kk * 64 + 4);
        u64 b2[4] = {tb0.x, tb0.y, tb1.x, tb1.y};
        float a[8] = {ta0.x, ta0.y, ta0.z, ta0.w, ta1.x, ta1.y, ta1.z, ta1.w};
#pragma unroll
        for (int i = 0; i < 8; i++) {
            u64 ar = rep2(a[i]);
#pragma unroll
            for (int j = 0; j < 4; j++) fma2(acc[i][j], ar, b2[j]);
        }
    }

#pragma unroll
    for (int i = 0; i < 8; i++) {
        ulonglong2* dst = (ulonglong2*)(g_y1 + (size_t)(row0 + rg * 8 + i) * C1O + cg * 8);
        dst[0] = make_ulonglong2(acc[i][0], acc[i][1]);
        dst[1] = make_ulonglong2(acc[i][2], acc[i][3]);
    }

    __syncthreads();
    float* redS = Xsh;
    float* redQ = Xsh + 32 * C1O;
#pragma unroll
    for (int jp = 0; jp < 4; jp++) {
        float sx = 0.f, sy = 0.f, qx = 0.f, qy = 0.f;
#pragma unroll
        for (int i = 0; i < 8; i++) {
            float2 v = unp2(acc[i][jp]);
            sx += v.x; sy += v.y; qx += v.x * v.x; qy += v.y * v.y;
        }
        redS[rg * C1O + cg * 8 + 2 * jp]     = sx;
        redS[rg * C1O + cg * 8 + 2 * jp + 1] = sy;
        redQ[rg * C1O + cg * 8 + 2 * jp]     = qx;
        redQ[rg * C1O + cg * 8 + 2 * jp + 1] = qy;
    }
    __syncthreads();
    if (tid < 2 * C1O) {
        int which = tid >> 6, c = tid & 63;
        const float* src = which ? redQ : redS;
        float s = 0.0f;
        for (int g = 0; g < 32; g++) s += src[g * C1O + c];
        g_part1[(size_t)which * NB01 * C1O + (size_t)blockIdx.x * C1O + c] = s;
    }
}

// ---------------------------------------------------------------------------
// Kernel 3: GEMM2 (64->128) + BN stats + fused max/min over K
// ---------------------------------------------------------------------------
__global__ __launch_bounds__(256, 2) void gemm_last_kernel(const float* __restrict__ W2) {
    extern __shared__ float sm[];
    float* Xsh = sm;                        // [64][128]
    float* Wsh = sm + 64 * 128;             // [64][128]
    float* scb = Wsh + 64 * 128;
    float* shb = scb + 64;
    int tid = threadIdx.x;

    for (int e = tid; e < C2 * 64; e += 256) {
        int co = e >> 6, ci = e & 63;
        Wsh[ci * C2 + co] = W2[e];
    }
    if (tid < C1O) { scb[tid] = g_scale1[tid]; shb[tid] = g_shift1[tid]; }
    __syncthreads();

    int row0 = blockIdx.x * 128;
    {
        int r = tid >> 1, half = tid & 1;
        const float4* src = (const float4*)(g_y1 + (size_t)(row0 + r) * C1O + half * 32);
#pragma unroll
        for (int q = 0; q < 8; q++) {
            float4 v = src[q];
            int c = half * 32 + q * 4;
            v.x = fmaxf(0.0f, fmaf(v.x, scb[c + 0], shb[c + 0]));
            v.y = fmaxf(0.0f, fmaf(v.y, scb[c + 1], shb[c + 1]));
            v.z = fmaxf(0.0f, fmaf(v.z, scb[c + 2], shb[c + 2]));
            v.w = fmaxf(0.0f, fmaf(v.w, scb[c + 3], shb[c + 3]));
            Xsh[(c + 0) * 128 + r] = v.x;
            Xsh[(c + 1) * 128 + r] = v.y;
            Xsh[(c + 2) * 128 + r] = v.z;
            Xsh[(c + 3) * 128 + r] = v.w;
        }
    }
    __syncthreads();

    int cg = tid & 15, rg = tid >> 4;
    u64 acc[8][4];
#pragma unroll
    for (int i = 0; i < 8; i++)
#pragma unroll
        for (int j = 0; j < 4; j++) acc[i][j] = 0ull;

    const float* Xp = Xsh + rg * 8;
    const float* Wp = Wsh + cg * 8;
#pragma unroll 4
    for (int kk = 0; kk < 64; kk++) {
        float4 ta0 = *(const float4*)(Xp + kk * 128);
        float4 ta1 = *(const float4*)(Xp + kk * 128 + 4);
        ulonglong2 tb0 = *(const ulonglong2*)(Wp + kk * C2);
        ulonglong2 tb1 = *(const ulonglong2*)(Wp + kk * C2 + 4);
        u64 b2[4] = {tb0.x, tb0.y, tb1.x, tb1.y};
        float a[8] = {ta0.x, ta0.y, ta0.z, ta0.w, ta1.x, ta1.y, ta1.z, ta1.w};
#pragma unroll
        for (int i = 0; i < 8; i++) {
            u64 ar = rep2(a[i]);
#pragma unroll
            for (int j = 0; j < 4; j++) fma2(acc[i][j], ar, b2[j]);
        }
    }

    // unpack to scalar view for epilogues
    float av[8][8];
#pragma unroll
    for (int i = 0; i < 8; i++)
#pragma unroll
        for (int jp = 0; jp < 4; jp++) {
            float2 v = unp2(acc[i][jp]);
            av[i][2 * jp] = v.x; av[i][2 * jp + 1] = v.y;
        }

    // --- Phase A: BN stats partials ---
    __syncthreads();
    float* redS = Xsh;                 // [16][128]
    float* redQ = Xsh + 16 * C2;       // [16][128]
#pragma unroll
    for (int j = 0; j < 8; j++) {
        float s = 0.0f, q = 0.0f;
#pragma unroll
        for (int i = 0; i < 8; i++) { float v = av[i][j]; s += v; q += v * v; }
        redS[rg * C2 + cg * 8 + j] = s;
        redQ[rg * C2 + cg * 8 + j] = q;
    }
    __syncthreads();
    {
        int which = tid >> 7, c = tid & 127;
        const float* src = which ? redQ : redS;
        float s = 0.0f;
        for (int g = 0; g < 16; g++) s += src[g * C2 + c];
        g_part2[(size_t)which * NB2 * C2 + (size_t)blockIdx.x * C2 + c] = s;
    }

    // --- Phase B: max/min over K ---
    __syncthreads();
    float* redM = Xsh;
    float* redN = Xsh + 16 * C2;
#pragma unroll
    for (int j = 0; j < 8; j++) {
        float mx = av[0][j], mn = av[0][j];
#pragma unroll
        for (int i = 1; i < 8; i++) { mx = fmaxf(mx, av[i][j]); mn = fminf(mn, av[i][j]); }
        redM[rg * C2 + cg * 8 + j] = mx;
        redN[rg * C2 + cg * 8 + j] = mn;
    }
    __syncthreads();
    for (int e = tid; e < 4 * C2; e += 256) {
        int g = e >> 7, c = e & 127;
        float mx = redM[(4 * g + 0) * C2 + c];
        float mn = redN[(4 * g + 0) * C2 + c];
#pragma unroll
        for (int t = 1; t < 4; t++) {
            mx = fmaxf(mx, redM[(4 * g + t) * C2 + c]);
            mn = fminf(mn, redN[(4 * g + t) * C2 + c]);
        }
        int b  = row0 >> 15;
        int n2 = ((row0 >> 5) & (N2_ - 1)) + g;
        size_t o = (size_t)(b * N2_ + n2) * C2 + c;
        g_max2[o] = mx;
        g_min2[o] = mn;
    }
}

// ---------------------------------------------------------------------------
// Stats finalize
// ---------------------------------------------------------------------------
__global__ void stats_kernel(int layer, const float* __restrict__ gamma,
                             const float* __restrict__ beta) {
    const float* part; int nb, C; float* scale; float* shift;
    if (layer == 0)      { part = g_part0; nb = NB01; C = C0;  scale = g_scale0; shift = g_shift0; }
    else if (layer == 1) { part = g_part1; nb = NB01; C = C1O; scale = g_scale1; shift = g_shift1; }
    else                 { part = g_part2; nb = NB2;  C = C2;  scale = g_scale2; shift = g_shift2; }

    __shared__ float shs[256], shq[256];
    int c = blockIdx.x;
    int tid = threadIdx.x;
    float s = 0.0f, q = 0.0f;
    for (int i = tid; i < nb; i += 256) {
        s += part[(size_t)i * C + c];
        q += part[(size_t)(nb + i) * C + c];
    }
    shs[tid] = s; shq[tid] = q;
    __syncthreads();
    for (int off = 128; off > 0; off >>= 1) {
        if (tid < off) { shs[tid] += shs[tid + off]; shq[tid] += shq[tid + off]; }
        __syncthreads();
    }
    if (tid == 0) {
        float mean = shs[0] / CNT_;
        float var  = shq[0] / CNT_ - mean * mean;
        float sc   = gamma[c] * rsqrtf(var + EPS_);
        scale[c] = sc;
        shift[c] = beta[c] - mean * sc;
    }
}

// ---------------------------------------------------------------------------
// Final output
// ---------------------------------------------------------------------------
__global__ void final_kernel(float* __restrict__ out) {
    int o = blockIdx.x * 256 + threadIdx.x;
    if (o >= B_ * C2 * N2_) return;
    int n2 = o & (N2_ - 1);
    int c  = (o >> 10) & (C2 - 1);
    int b  = o >> 17;
    float sc = g_scale2[c], sh = g_shift2[c];
    size_t mi = (size_t)(b * N2_ + n2) * C2 + c;
    float v = (sc >= 0.0f) ? g_max2[mi] : g_min2[mi];
    out[o] = fmaxf(0.0f, fmaf(sc, v, sh));
}

// ---------------------------------------------------------------------------
// Launcher
// ---------------------------------------------------------------------------
extern "C" void kernel_launch(void* const* d_in, const int* in_sizes, int n_in,
                              void* d_out, int out_size) {
    const float* in_xyz     = (const float*)d_in[0];
    const float* out_xyz    = (const float*)d_in[1];
    const float* in_feature = (const float*)d_in[2];
    const int*   nbr        = (const int*)  d_in[3];
    const float* W0 = (const float*)d_in[4];
    const float* g0 = (const float*)d_in[5];
    const float* b0 = (const float*)d_in[6];
    const float* W1 = (const float*)d_in[7];
    const float* g1 = (const float*)d_in[8];
    const float* b1 = (const float*)d_in[9];
    const float* W2 = (const float*)d_in[10];
    const float* g2 = (const float*)d_in[11];
    const float* b2 = (const float*)d_in[12];
    float* out = (float*)d_out;

    const int SM0B = (CPAD * 256 + CPAD * 64) * 4;            // 87040
    const int SM1B = (64 * 256 + 64 * 64 + 128) * 4;          // 82432
    const int SM2B = (64 * 128 + 64 * 128 + 128) * 4;         // 66048

    cudaFuncSetAttribute(gemm0_kernel,    cudaFuncAttributeMaxDynamicSharedMemorySize, SM0B);
    cudaFuncSetAttribute(gemm_mid_kernel, cudaFuncAttributeMaxDynamicSharedMemorySize, SM1B);
    cudaFuncSetAttribute(gemm_last_kernel,cudaFuncAttributeMaxDynamicSharedMemorySize, SM2B);

    transpose_kernel<<<dim3(N1_ / 32, B_), dim3(32, 8)>>>(in_feature, in_xyz);
    oxyz_kernel<<<(B_ * N2_ + 255) / 256, 256>>>(out_xyz);

    gemm0_kernel<<<NB01, 256, SM0B>>>(nbr, W0);
    stats_kernel<<<C0, 256>>>(0, g0, b0);

    gemm_mid_kernel<<<NB01, 256, SM1B>>>(W1);
    stats_kernel<<<C1O, 256>>>(1, g1, b1);

    gemm_last_kernel<<<NB2, 256, SM2B>>>(W2);
    stats_kernel<<<C2, 256>>>(2, g2, b2);

    final_kernel<<<(B_ * C2 * N2_ + 255) / 256, 256>>>(out);
}

// round 11
// speedup vs baseline: 2.4715x; 1.5296x over previous
#include <cuda_runtime.h>
#include <cuda_bf16.h>
#include <math.h>
#include <cstdint>

// ---------------------------------------------------------------------------
// Problem constants
// ---------------------------------------------------------------------------
#define B_    16
#define N1_   4096
#define N2_   1024
#define KNB   32
#define CIN0  67
#define CPAD  68
#define C0    64
#define C1O   64
#define C2    128
#define M_    (B_ * N2_ * KNB)     // 524288
#define NB01  (M_ / 256)           // 2048  (gemm0 blocks)
#define NBT   (M_ / 128)           // 4096  (mma gemm blocks)
#define CNT_  524288.0f
#define EPS_  1e-5f

typedef unsigned long long u64;

// ---------------------------------------------------------------------------
// FFMA2 helpers (gemm0 path)
// ---------------------------------------------------------------------------
__device__ __forceinline__ void fma2(u64& d, u64 a, u64 b) {
    asm("fma.rn.f32x2 %0, %1, %2, %0;" : "+l"(d) : "l"(a), "l"(b));
}
__device__ __forceinline__ u64 rep2(float x) {
    u64 r; asm("mov.b64 %0, {%1, %1};" : "=l"(r) : "f"(x)); return r;
}
__device__ __forceinline__ float2 unp2(u64 v) {
    float2 f; asm("mov.b64 {%0, %1}, %2;" : "=f"(f.x), "=f"(f.y) : "l"(v)); return f;
}

// ---------------------------------------------------------------------------
// mma.sync helpers (baseline PTX, works on compute_103)
// ---------------------------------------------------------------------------
__device__ __forceinline__ void mma_bf16(float* d, const uint32_t* a, const uint32_t* b) {
    asm volatile(
        "mma.sync.aligned.m16n8k16.row.col.f32.bf16.bf16.f32 "
        "{%0,%1,%2,%3}, {%4,%5,%6,%7}, {%8,%9}, {%0,%1,%2,%3};"
        : "+f"(d[0]), "+f"(d[1]), "+f"(d[2]), "+f"(d[3])
        : "r"(a[0]), "r"(a[1]), "r"(a[2]), "r"(a[3]), "r"(b[0]), "r"(b[1]));
}

// swizzled 32-bit load from a bf16 tile with 128-byte rows (64 bf16/row)
__device__ __forceinline__ uint32_t lds_sw(const char* base, int row, int k) {
    uint32_t byte = (uint32_t)(row * 128 + k * 2);
    byte ^= (byte >> 3) & 0x70;
    return *(const uint32_t*)(base + byte);
}

#define SMEM_SWIZZLE_128B(b) ((b) ^ (((b) >> 3) & 0x70))

// bf16 hi/lo split of two fp32 values, packed as bf16x2 words
__device__ __forceinline__ void split2(float a, float b, uint32_t& hi, uint32_t& lo) {
    __nv_bfloat16 ha = __float2bfloat16(a), hb = __float2bfloat16(b);
    __nv_bfloat16 la = __float2bfloat16(a - __bfloat162float(ha));
    __nv_bfloat16 lb = __float2bfloat16(b - __bfloat162float(hb));
    hi = (uint32_t)__bfloat16_as_ushort(ha) | ((uint32_t)__bfloat16_as_ushort(hb) << 16);
    lo = (uint32_t)__bfloat16_as_ushort(la) | ((uint32_t)__bfloat16_as_ushort(lb) << 16);
}

// ---------------------------------------------------------------------------
// Scratch
// ---------------------------------------------------------------------------
__device__ float g_xallT[B_ * N1_ * CPAD];
__device__ float g_oxyz [B_ * N2_ * 4];
__device__ float g_y0[(size_t)M_ * C0];
__device__ float g_y1[(size_t)M_ * C1O];
__device__ float g_part0[2 * NB01 * C0];
__device__ float g_part1[2 * NBT * C1O];
__device__ float g_part2[2 * NBT * C2];
__device__ float g_scale0[C0],  g_shift0[C0];
__device__ float g_scale1[C1O], g_shift1[C1O];
__device__ float g_scale2[C2],  g_shift2[C2];
__device__ float g_max2[B_ * N2_ * C2];
__device__ float g_min2[B_ * N2_ * C2];

// ---------------------------------------------------------------------------
// Fused pre: transpose feat+xyz -> [B][N1][68], plus oxyz pack
// ---------------------------------------------------------------------------
__global__ void fused_pre_kernel(const float* __restrict__ in_feature,
                                 const float* __restrict__ in_xyz,
                                 const float* __restrict__ out_xyz) {
    int b  = blockIdx.y;
    int tx = threadIdx.x;
    int ty = threadIdx.y;
    int tid = ty * 32 + tx;

    if (blockIdx.x == N1_ / 32) {
        for (int n2 = tid; n2 < N2_; n2 += 256) {
            int i = b * N2_ + n2;
            g_oxyz[i * 4 + 0] = out_xyz[(b * 3 + 0) * N2_ + n2];
            g_oxyz[i * 4 + 1] = out_xyz[(b * 3 + 1) * N2_ + n2];
            g_oxyz[i * 4 + 2] = out_xyz[(b * 3 + 2) * N2_ + n2];
            g_oxyz[i * 4 + 3] = 0.0f;
        }
        return;
    }

    __shared__ float tile[CPAD][33];
    int n0 = blockIdx.x * 32;
    for (int c = ty; c < CPAD; c += 8) {
        float v;
        if (c < 64)      v = in_feature[((size_t)b * 64 + c) * N1_ + n0 + tx];
        else if (c < 67) v = in_xyz[((size_t)b * 3 + (c - 64)) * N1_ + n0 + tx];
        else             v = 0.0f;
        tile[c][tx] = v;
    }
    __syncthreads();
    for (int e = tid; e < 32 * CPAD; e += 256) {
        int nl = e / CPAD;
        int c  = e % CPAD;
        g_xallT[((size_t)(b * N1_ + n0 + nl)) * CPAD + c] = tile[c][nl];
    }
}

// ---------------------------------------------------------------------------
// Kernel 1: gather + GEMM0 (68 -> 64) + BN stat partials (FFMA2 path)
// ---------------------------------------------------------------------------
__global__ __launch_bounds__(256, 2) void gemm0_kernel(const int* __restrict__ nbr,
                                                       const float* __restrict__ W0) {
    extern __shared__ float sm[];
    float* Xsh = sm;                    // [CPAD][256]
    float* Wsh = sm + CPAD * 256;       // [CPAD][64]
    int tid = threadIdx.x;

    for (int e = tid; e < C0 * CIN0; e += 256) {
        int co = e / CIN0, ci = e % CIN0;
        Wsh[ci * C0 + co] = W0[e];
    }
    if (tid < C0) Wsh[67 * C0 + tid] = 0.0f;

    int row0 = blockIdx.x * 256;
    {
        int R   = row0 + tid;
        int b   = R >> 15;
        int n2  = (R >> 5) & (N2_ - 1);
        int idx = nbr[R];
        const float4* src = (const float4*)(g_xallT + (size_t)(b * N1_ + idx) * CPAD);
        const float4  oz  = *(const float4*)(g_oxyz + (size_t)(b * N2_ + n2) * 4);
#pragma unroll
        for (int q = 0; q < 17; q++) {
            float4 v = src[q];
            if (q == 16) { v.x -= oz.x; v.y -= oz.y; v.z -= oz.z; v.w = 0.0f; }
            Xsh[(q * 4 + 0) * 256 + tid] = v.x;
            Xsh[(q * 4 + 1) * 256 + tid] = v.y;
            Xsh[(q * 4 + 2) * 256 + tid] = v.z;
            Xsh[(q * 4 + 3) * 256 + tid] = v.w;
        }
    }
    __syncthreads();

    int cg = tid & 7, rg = tid >> 3;
    u64 acc[8][4];
#pragma unroll
    for (int i = 0; i < 8; i++)
#pragma unroll
        for (int j = 0; j < 4; j++) acc[i][j] = 0ull;

    const float* Xp = Xsh + rg * 8;
    const float* Wp = Wsh + cg * 8;
#pragma unroll 4
    for (int kk = 0; kk < CPAD; kk++) {
        float4 ta0 = *(const float4*)(Xp + kk * 256);
        float4 ta1 = *(const float4*)(Xp + kk * 256 + 4);
        ulonglong2 tb0 = *(const ulonglong2*)(Wp + kk * C0);
        ulonglong2 tb1 = *(const ulonglong2*)(Wp + kk * C0 + 4);
        u64 b2[4] = {tb0.x, tb0.y, tb1.x, tb1.y};
        float a[8] = {ta0.x, ta0.y, ta0.z, ta0.w, ta1.x, ta1.y, ta1.z, ta1.w};
#pragma unroll
        for (int i = 0; i < 8; i++) {
            u64 ar = rep2(a[i]);
#pragma unroll
            for (int j = 0; j < 4; j++) fma2(acc[i][j], ar, b2[j]);
        }
    }

#pragma unroll
    for (int i = 0; i < 8; i++) {
        ulonglong2* dst = (ulonglong2*)(g_y0 + (size_t)(row0 + rg * 8 + i) * C0 + cg * 8);
        dst[0] = make_ulonglong2(acc[i][0], acc[i][1]);
        dst[1] = make_ulonglong2(acc[i][2], acc[i][3]);
    }

    __syncthreads();
    float* redS = Xsh;
    float* redQ = Xsh + 32 * C0;
#pragma unroll
    for (int jp = 0; jp < 4; jp++) {
        float sx = 0.f, sy = 0.f, qx = 0.f, qy = 0.f;
#pragma unroll
        for (int i = 0; i < 8; i++) {
            float2 v = unp2(acc[i][jp]);
            sx += v.x; sy += v.y; qx += v.x * v.x; qy += v.y * v.y;
        }
        redS[rg * C0 + cg * 8 + 2 * jp]     = sx;
        redS[rg * C0 + cg * 8 + 2 * jp + 1] = sy;
        redQ[rg * C0 + cg * 8 + 2 * jp]     = qx;
        redQ[rg * C0 + cg * 8 + 2 * jp + 1] = qy;
    }
    __syncthreads();
    if (tid < 2 * C0) {
        int which = tid >> 6, c = tid & 63;
        const float* src = which ? redQ : redS;
        float s = 0.0f;
        for (int g = 0; g < 32; g++) s += src[g * C0 + c];
        g_part0[(size_t)which * NB01 * C0 + (size_t)blockIdx.x * C0 + c] = s;
    }
}

// ---------------------------------------------------------------------------
// GEMM1 (mma.sync): y1 = relu(bn0(y0)) @ W1^T, 128-row tiles, bf16 split
// smem: scb/shb 1KB | Xhi 16K | Xlo 16K | Whi 8K | Wlo 8K = 50176 B
// ---------------------------------------------------------------------------
#define T1_SCB  0
#define T1_SHB  512
#define T1_XHI  1024
#define T1_XLO  17408
#define T1_WHI  33792
#define T1_WLO  41984
#define T1_SMEM 50176

__global__ __launch_bounds__(256, 3) void gemm1t_kernel(const float* __restrict__ W1) {
    extern __shared__ char smc[];
    float* scb = (float*)(smc + T1_SCB);
    float* shb = (float*)(smc + T1_SHB);
    int tid = threadIdx.x;
    int wid = tid >> 5, lane = tid & 31;

    if (tid < 64) { scb[tid] = g_scale0[tid]; shb[tid] = g_shift0[tid]; }
    __syncthreads();

    // W1 [64][64] -> Whi/Wlo swizzled (rows = cout, cols = cin)
    for (int e = tid; e < 64 * 64; e += 256) {
        int n = e >> 6, k = e & 63;
        float wv = W1[e];
        __nv_bfloat16 h = __float2bfloat16(wv);
        __nv_bfloat16 l = __float2bfloat16(wv - __bfloat162float(h));
        uint32_t byte = (uint32_t)(n * 128 + k * 2);
        uint32_t sw = SMEM_SWIZZLE_128B(byte);
        *(__nv_bfloat16*)(smc + T1_WHI + sw) = h;
        *(__nv_bfloat16*)(smc + T1_WLO + sw) = l;
    }

    // X tile: 128 rows x 64 cols of relu(bn0(y0)) -> Xhi/Xlo swizzled
    {
        const char* ytile = (const char*)(g_y0 + (size_t)blockIdx.x * 128 * 64);
#pragma unroll
        for (int q = 0; q < 8; q++) {
            int bo = wid * 4096 + q * 512 + lane * 16;
            float4 v = *(const float4*)(ytile + bo);
            int r = bo >> 8;
            int c = (bo & 255) >> 2;
            float x0 = fmaxf(0.f, fmaf(v.x, scb[c + 0], shb[c + 0]));
            float x1 = fmaxf(0.f, fmaf(v.y, scb[c + 1], shb[c + 1]));
            float x2 = fmaxf(0.f, fmaf(v.z, scb[c + 2], shb[c + 2]));
            float x3 = fmaxf(0.f, fmaf(v.w, scb[c + 3], shb[c + 3]));
            uint2 ph, pl;
            split2(x0, x1, ph.x, pl.x);
            split2(x2, x3, ph.y, pl.y);
            uint32_t byte = (uint32_t)(r * 128 + c * 2);
            uint32_t sw = SMEM_SWIZZLE_128B(byte);
            *(uint2*)(smc + T1_XHI + sw) = ph;
            *(uint2*)(smc + T1_XLO + sw) = pl;
        }
    }
    __syncthreads();

    // warp wid -> rows [wid*16, wid*16+16); full N=64 (8 n-tiles)
    int g  = lane >> 2;
    int kq = (lane & 3) * 2;
    int rbase = wid * 16;

    float acc[8][4];
#pragma unroll
    for (int n = 0; n < 8; n++)
#pragma unroll
        for (int j = 0; j < 4; j++) acc[n][j] = 0.0f;

    const char* APASS[3] = {smc + T1_XHI, smc + T1_XHI, smc + T1_XLO};
    const char* BPASS[3] = {smc + T1_WHI, smc + T1_WLO, smc + T1_WHI};
#pragma unroll
    for (int p = 0; p < 3; p++) {
        const char* Ab = APASS[p];
        const char* Bb = BPASS[p];
#pragma unroll
        for (int kk = 0; kk < 64; kk += 16) {
            uint32_t a[4];
            a[0] = lds_sw(Ab, rbase + g,     kk + kq);
            a[1] = lds_sw(Ab, rbase + g + 8, kk + kq);
            a[2] = lds_sw(Ab, rbase + g,     kk + kq + 8);
            a[3] = lds_sw(Ab, rbase + g + 8, kk + kq + 8);
#pragma unroll
            for (int nt = 0; nt < 8; nt++) {
                uint32_t b[2];
                b[0] = lds_sw(Bb, nt * 8 + g, kk + kq);
                b[1] = lds_sw(Bb, nt * 8 + g, kk + kq + 8);
                mma_bf16(acc[nt], a, b);
            }
        }
    }

    // stage raw y1 into smem [128][64] (reuses Xhi/Xlo region, 32KB)
    __syncthreads();
    float* ystage = (float*)(smc + T1_XHI);
    {
        int cq = (lane & 3) * 2;
#pragma unroll
        for (int nt = 0; nt < 8; nt++) {
            *(float2*)(ystage + (rbase + g)     * 64 + nt * 8 + cq) = make_float2(acc[nt][0], acc[nt][1]);
            *(float2*)(ystage + (rbase + g + 8) * 64 + nt * 8 + cq) = make_float2(acc[nt][2], acc[nt][3]);
        }
    }
    __syncthreads();

    // coalesced global write of y1
    {
        float* dst = g_y1 + (size_t)blockIdx.x * 128 * 64;
#pragma unroll
        for (int q = 0; q < 8; q++) {
            int f = q * 256 + tid;
            *(float4*)(dst + f * 4) = *(const float4*)(ystage + f * 4);
        }
    }

    // BN stats partials
    float* redS = (float*)(smc + T1_WHI);
    float* redQ = redS + 256;
    {
        int col = tid & 63, grp = tid >> 6;
        float s = 0.f, q = 0.f;
        for (int r = grp * 32; r < grp * 32 + 32; r++) {
            float v = ystage[r * 64 + col];
            s += v; q += v * v;
        }
        redS[grp * 64 + col] = s;
        redQ[grp * 64 + col] = q;
    }
    __syncthreads();
    if (tid < 128) {
        int which = tid >> 6, c = tid & 63;
        const float* src = which ? redQ : redS;
        float s = src[c] + src[64 + c] + src[128 + c] + src[192 + c];
        g_part1[(size_t)which * NBT * C1O + (size_t)blockIdx.x * C1O + c] = s;
    }
}

// ---------------------------------------------------------------------------
// GEMM2 (mma.sync): y2 = relu(bn1(y1)) @ W2^T, N=128, fused stats + max/min
// smem: scb/shb 1KB | Xhi 16K | Xlo 16K | Whi 16K | Wlo 16K | red 4K = 70656 B
// ---------------------------------------------------------------------------
#define T2_SCB  0
#define T2_SHB  512
#define T2_XHI  1024
#define T2_XLO  17408
#define T2_WHI  33792
#define T2_WLO  50176
#define T2_RED  66560
#define T2_SMEM 70656

__global__ __launch_bounds__(256, 2) void gemm2t_kernel(const float* __restrict__ W2) {
    extern __shared__ char smc[];
    float* scb = (float*)(smc + T2_SCB);
    float* shb = (float*)(smc + T2_SHB);
    int tid = threadIdx.x;
    int wid = tid >> 5, lane = tid & 31;

    if (tid < 64) { scb[tid] = g_scale1[tid]; shb[tid] = g_shift1[tid]; }
    __syncthreads();

    // W2 [128][64] -> Whi/Wlo swizzled
    for (int e = tid; e < 128 * 64; e += 256) {
        int n = e >> 6, k = e & 63;
        float wv = W2[e];
        __nv_bfloat16 h = __float2bfloat16(wv);
        __nv_bfloat16 l = __float2bfloat16(wv - __bfloat162float(h));
        uint32_t byte = (uint32_t)(n * 128 + k * 2);
        uint32_t sw = SMEM_SWIZZLE_128B(byte);
        *(__nv_bfloat16*)(smc + T2_WHI + sw) = h;
        *(__nv_bfloat16*)(smc + T2_WLO + sw) = l;
    }

    // X tile from y1 -> Xhi/Xlo
    {
        const char* ytile = (const char*)(g_y1 + (size_t)blockIdx.x * 128 * 64);
#pragma unroll
        for (int q = 0; q < 8; q++) {
            int bo = wid * 4096 + q * 512 + lane * 16;
            float4 v = *(const float4*)(ytile + bo);
            int r = bo >> 8;
            int c = (bo & 255) >> 2;
            float x0 = fmaxf(0.f, fmaf(v.x, scb[c + 0], shb[c + 0]));
            float x1 = fmaxf(0.f, fmaf(v.y, scb[c + 1], shb[c + 1]));
            float x2 = fmaxf(0.f, fmaf(v.z, scb[c + 2], shb[c + 2]));
            float x3 = fmaxf(0.f, fmaf(v.w, scb[c + 3], shb[c + 3]));
            uint2 ph, pl;
            split2(x0, x1, ph.x, pl.x);
            split2(x2, x3, ph.y, pl.y);
            uint32_t byte = (uint32_t)(r * 128 + c * 2);
            uint32_t sw = SMEM_SWIZZLE_128B(byte);
            *(uint2*)(smc + T2_XHI + sw) = ph;
            *(uint2*)(smc + T2_XLO + sw) = pl;
        }
    }
    __syncthreads();

    // 8 warps = 4 (M) x 2 (N): rows mw*32..+31 (2 m-tiles), cols nw*64..+63 (8 n-tiles)
    int mw = wid & 3, nw = wid >> 2;
    int g  = lane >> 2;
    int kq = (lane & 3) * 2;

    float acc[2][8][4];
#pragma unroll
    for (int mt = 0; mt < 2; mt++)
#pragma unroll
        for (int n = 0; n < 8; n++)
#pragma unroll
            for (int j = 0; j < 4; j++) acc[mt][n][j] = 0.0f;

    const char* APASS[3] = {smc + T2_XHI, smc + T2_XHI, smc + T2_XLO};
    const char* BPASS[3] = {smc + T2_WHI, smc + T2_WLO, smc + T2_WHI};
#pragma unroll
    for (int p = 0; p < 3; p++) {
        const char* Ab = APASS[p];
        const char* Bb = BPASS[p];
#pragma unroll
        for (int kk = 0; kk < 64; kk += 16) {
            uint32_t a[2][4];
#pragma unroll
            for (int mt = 0; mt < 2; mt++) {
                int rb = mw * 32 + mt * 16;
                a[mt][0] = lds_sw(Ab, rb + g,     kk + kq);
                a[mt][1] = lds_sw(Ab, rb + g + 8, kk + kq);
                a[mt][2] = lds_sw(Ab, rb + g,     kk + kq + 8);
                a[mt][3] = lds_sw(Ab, rb + g + 8, kk + kq + 8);
            }
#pragma unroll
            for (int nt = 0; nt < 8; nt++) {
                uint32_t b[2];
                b[0] = lds_sw(Bb, nw * 64 + nt * 8 + g, kk + kq);
                b[1] = lds_sw(Bb, nw * 64 + nt * 8 + g, kk + kq + 8);
                mma_bf16(acc[0][nt], a[0], b);
                mma_bf16(acc[1][nt], a[1], b);
            }
        }
    }

    // stage raw y2 into smem [128][128] (reuses X/W regions, 64KB)
    __syncthreads();
    float* ystage = (float*)(smc + T2_XHI);
    {
        int cq = (lane & 3) * 2;
#pragma unroll
        for (int mt = 0; mt < 2; mt++) {
            int rb = mw * 32 + mt * 16;
#pragma unroll
            for (int nt = 0; nt < 8; nt++) {
                int col = nw * 64 + nt * 8 + cq;
                *(float2*)(ystage + (rb + g)     * 128 + col) = make_float2(acc[mt][nt][0], acc[mt][nt][1]);
                *(float2*)(ystage + (rb + g + 8) * 128 + col) = make_float2(acc[mt][nt][2], acc[mt][nt][3]);
            }
        }
    }
    __syncthreads();

    // fused: BN stat partials + max/min per 32-row K-group
    float* redS = (float*)(smc + T2_RED);
    float* redQ = redS + 512;
    {
        int row0 = blockIdx.x * 128;
        int b   = row0 >> 15;
        int n2b = (row0 >> 5) & (N2_ - 1);
        int col = tid & 127;
#pragma unroll
        for (int gi = 0; gi < 2; gi++) {
            int grp = ((tid >> 7) << 1) + gi;
            float v0 = ystage[(grp * 32) * 128 + col];
            float s = 0.f, q = 0.f, mx = v0, mn = v0;
            for (int r = grp * 32; r < grp * 32 + 32; r++) {
                float v = ystage[r * 128 + col];
                s += v; q += v * v;
                mx = fmaxf(mx, v); mn = fminf(mn, v);
            }
            redS[grp * 128 + col] = s;
            redQ[grp * 128 + col] = q;
            size_t o = (size_t)(b * N2_ + n2b + grp) * C2 + col;
            g_max2[o] = mx;
            g_min2[o] = mn;
        }
    }
    __syncthreads();
    {
        int which = tid >> 7, c = tid & 127;
        const float* src = which ? redQ : redS;
        float s = src[c] + src[128 + c] + src[256 + c] + src[384 + c];
        g_part2[(size_t)which * NBT * C2 + (size_t)blockIdx.x * C2 + c] = s;
    }
}

// ---------------------------------------------------------------------------
// Stats finalize
// ---------------------------------------------------------------------------
__global__ void stats_kernel(int layer, const float* __restrict__ gamma,
                             const float* __restrict__ beta) {
    const float* part; int nb, C; float* scale; float* shift;
    if (layer == 0)      { part = g_part0; nb = NB01; C = C0;  scale = g_scale0; shift = g_shift0; }
    else if (layer == 1) { part = g_part1; nb = NBT;  C = C1O; scale = g_scale1; shift = g_shift1; }
    else                 { part = g_part2; nb = NBT;  C = C2;  scale = g_scale2; shift = g_shift2; }

    __shared__ float shs[256], shq[256];
    int c = blockIdx.x;
    int tid = threadIdx.x;
    float s = 0.0f, q = 0.0f;
    for (int i = tid; i < nb; i += 256) {
        s += part[(size_t)i * C + c];
        q += part[(size_t)(nb + i) * C + c];
    }
    shs[tid] = s; shq[tid] = q;
    __syncthreads();
    for (int off = 128; off > 0; off >>= 1) {
        if (tid < off) { shs[tid] += shs[tid + off]; shq[tid] += shq[tid + off]; }
        __syncthreads();
    }
    if (tid == 0) {
        float mean = shs[0] / CNT_;
        float var  = shq[0] / CNT_ - mean * mean;
        float sc   = gamma[c] * rsqrtf(var + EPS_);
        scale[c] = sc;
        shift[c] = beta[c] - mean * sc;
    }
}

// ---------------------------------------------------------------------------
// Final output
// ---------------------------------------------------------------------------
__global__ void final_kernel(float* __restrict__ out) {
    int o = blockIdx.x * 256 + threadIdx.x;
    if (o >= B_ * C2 * N2_) return;
    int n2 = o & (N2_ - 1);
    int c  = (o >> 10) & (C2 - 1);
    int b  = o >> 17;
    float sc = g_scale2[c], sh = g_shift2[c];
    size_t mi = (size_t)(b * N2_ + n2) * C2 + c;
    float v = (sc >= 0.0f) ? g_max2[mi] : g_min2[mi];
    out[o] = fmaxf(0.0f, fmaf(sc, v, sh));
}

// ---------------------------------------------------------------------------
// Launcher
// ---------------------------------------------------------------------------
extern "C" void kernel_launch(void* const* d_in, const int* in_sizes, int n_in,
                              void* d_out, int out_size) {
    const float* in_xyz     = (const float*)d_in[0];
    const float* out_xyz    = (const float*)d_in[1];
    const float* in_feature = (const float*)d_in[2];
    const int*   nbr        = (const int*)  d_in[3];
    const float* W0 = (const float*)d_in[4];
    const float* g0 = (const float*)d_in[5];
    const float* b0 = (const float*)d_in[6];
    const float* W1 = (const float*)d_in[7];
    const float* g1 = (const float*)d_in[8];
    const float* b1 = (const float*)d_in[9];
    const float* W2 = (const float*)d_in[10];
    const float* g2 = (const float*)d_in[11];
    const float* b2 = (const float*)d_in[12];
    float* out = (float*)d_out;

    const int SM0B = (CPAD * 256 + CPAD * 64) * 4;            // 87040

    cudaFuncSetAttribute(gemm0_kernel,  cudaFuncAttributeMaxDynamicSharedMemorySize, SM0B);
    cudaFuncSetAttribute(gemm1t_kernel, cudaFuncAttributeMaxDynamicSharedMemorySize, T1_SMEM);
    cudaFuncSetAttribute(gemm2t_kernel, cudaFuncAttributeMaxDynamicSharedMemorySize, T2_SMEM);

    // launch order keeps gemm2t at index 5 for the fixed ncu -s 5 -c 1 window
    fused_pre_kernel<<<dim3(N1_ / 32 + 1, B_), dim3(32, 8)>>>(in_feature, in_xyz, out_xyz);

    gemm0_kernel<<<NB01, 256, SM0B>>>(nbr, W0);
    stats_kernel<<<C0, 256>>>(0, g0, b0);

    gemm1t_kernel<<<NBT, 256, T1_SMEM>>>(W1);
    stats_kernel<<<C1O, 256>>>(1, g1, b1);

    gemm2t_kernel<<<NBT, 256, T2_SMEM>>>(W2);
    stats_kernel<<<C2, 256>>>(2, g2, b2);

    final_kernel<<<(B_ * C2 * N2_ + 255) / 256, 256>>>(out);
}

// round 12
// speedup vs baseline: 2.6857x; 1.0867x over previous
#include <cuda_runtime.h>
#include <cuda_bf16.h>
#include <math.h>
#include <cstdint>

// ---------------------------------------------------------------------------
// Problem constants
// ---------------------------------------------------------------------------
#define B_    16
#define N1_   4096
#define N2_   1024
#define KNB   32
#define CIN0  67
#define CPAD  68
#define C0    64
#define C1O   64
#define C2    128
#define M_    (B_ * N2_ * KNB)     // 524288
#define NBT   (M_ / 128)           // 4096  (mma gemm blocks)
#define CNT_  524288.0f
#define EPS_  1e-5f

// ---------------------------------------------------------------------------
// mma.sync / ldmatrix helpers (baseline PTX, works on compute_103)
// ---------------------------------------------------------------------------
__device__ __forceinline__ void mma_bf16(float* d, const uint32_t* a, const uint32_t* b) {
    asm volatile(
        "mma.sync.aligned.m16n8k16.row.col.f32.bf16.bf16.f32 "
        "{%0,%1,%2,%3}, {%4,%5,%6,%7}, {%8,%9}, {%0,%1,%2,%3};"
        : "+f"(d[0]), "+f"(d[1]), "+f"(d[2]), "+f"(d[3])
        : "r"(a[0]), "r"(a[1]), "r"(a[2]), "r"(a[3]), "r"(b[0]), "r"(b[1]));
}
__device__ __forceinline__ void ldsm_x4(uint32_t* r, uint32_t addr) {
    asm volatile("ldmatrix.sync.aligned.m8n8.x4.shared.b16 {%0,%1,%2,%3}, [%4];"
        : "=r"(r[0]), "=r"(r[1]), "=r"(r[2]), "=r"(r[3]) : "r"(addr));
}
// swizzled smem address for bf16 tiles with 128-byte rows (64 bf16/row)
__device__ __forceinline__ uint32_t sw_off(uint32_t base32, int row, int col) {
    uint32_t byte = (uint32_t)(row * 128 + col * 2);
    byte ^= (byte >> 3) & 0x70;
    return base32 + byte;
}
#define SMEM_SWIZZLE_128B(b) ((b) ^ (((b) >> 3) & 0x70))

// bf16 hi/lo split of two fp32 values, packed as bf16x2 words
__device__ __forceinline__ void split2(float a, float b, uint32_t& hi, uint32_t& lo) {
    __nv_bfloat16 ha = __float2bfloat16(a), hb = __float2bfloat16(b);
    __nv_bfloat16 la = __float2bfloat16(a - __bfloat162float(ha));
    __nv_bfloat16 lb = __float2bfloat16(b - __bfloat162float(hb));
    hi = (uint32_t)__bfloat16_as_ushort(ha) | ((uint32_t)__bfloat16_as_ushort(hb) << 16);
    lo = (uint32_t)__bfloat16_as_ushort(la) | ((uint32_t)__bfloat16_as_ushort(lb) << 16);
}

// ---------------------------------------------------------------------------
// Scratch
// ---------------------------------------------------------------------------
__device__ float g_xallT[B_ * N1_ * CPAD];
__device__ float g_oxyz [B_ * N2_ * 4];
__device__ float g_y0[(size_t)M_ * C0];
__device__ float g_y1[(size_t)M_ * C1O];
__device__ float g_part0[2 * NBT * C0];
__device__ float g_part1[2 * NBT * C1O];
__device__ float g_part2[2 * NBT * C2];
__device__ float g_scale0[C0],  g_shift0[C0];
__device__ float g_scale1[C1O], g_shift1[C1O];
__device__ float g_scale2[C2],  g_shift2[C2];
__device__ float g_max2[B_ * N2_ * C2];
__device__ float g_min2[B_ * N2_ * C2];

// ---------------------------------------------------------------------------
// Fused pre: transpose feat+xyz -> [B][N1][68], plus oxyz pack
// ---------------------------------------------------------------------------
__global__ void fused_pre_kernel(const float* __restrict__ in_feature,
                                 const float* __restrict__ in_xyz,
                                 const float* __restrict__ out_xyz) {
    int b  = blockIdx.y;
    int tx = threadIdx.x;
    int ty = threadIdx.y;
    int tid = ty * 32 + tx;

    if (blockIdx.x == N1_ / 32) {
        for (int n2 = tid; n2 < N2_; n2 += 256) {
            int i = b * N2_ + n2;
            g_oxyz[i * 4 + 0] = out_xyz[(b * 3 + 0) * N2_ + n2];
            g_oxyz[i * 4 + 1] = out_xyz[(b * 3 + 1) * N2_ + n2];
            g_oxyz[i * 4 + 2] = out_xyz[(b * 3 + 2) * N2_ + n2];
            g_oxyz[i * 4 + 3] = 0.0f;
        }
        return;
    }

    __shared__ float tile[CPAD][33];
    int n0 = blockIdx.x * 32;
    for (int c = ty; c < CPAD; c += 8) {
        float v;
        if (c < 64)      v = in_feature[((size_t)b * 64 + c) * N1_ + n0 + tx];
        else if (c < 67) v = in_xyz[((size_t)b * 3 + (c - 64)) * N1_ + n0 + tx];
        else             v = 0.0f;
        tile[c][tx] = v;
    }
    __syncthreads();
    for (int e = tid; e < 32 * CPAD; e += 256) {
        int nl = e / CPAD;
        int c  = e % CPAD;
        g_xallT[((size_t)(b * N1_ + n0 + nl)) * CPAD + c] = tile[c][nl];
    }
}

// ---------------------------------------------------------------------------
// GEMM0 (mma.sync): gather -> y0 = X(67ch) @ W0^T
// feature 64ch via bf16 split MMA; xyz 3ch via exact fp32 FFMA on fragments.
// smem: XYZ 2K | Wxyz 1K(pad) | Xhi 16K | Xlo 16K | Whi 8K | Wlo 8K = 53248 B
// ---------------------------------------------------------------------------
#define S0_XYZ   0
#define S0_WXYZ  2048
#define S0_XHI   4096
#define S0_XLO   20480
#define S0_WHI   36864
#define S0_WLO   45056
#define S0_SMEM  53248

__global__ __launch_bounds__(256, 3) void gemm0t_kernel(const int* __restrict__ nbr,
                                                        const float* __restrict__ W0) {
    extern __shared__ char smc[];
    float* XYZ  = (float*)(smc + S0_XYZ);    // [128][4]
    float* Wxyz = (float*)(smc + S0_WXYZ);   // [3][64]
    int tid = threadIdx.x;
    int wid = tid >> 5, lane = tid & 31;

    // W0 feature part [64 cout][64 cin] -> Whi/Wlo swizzled
    for (int e = tid; e < 64 * 64; e += 256) {
        int n = e >> 6, k = e & 63;
        float wv = W0[n * CIN0 + k];
        __nv_bfloat16 h = __float2bfloat16(wv);
        __nv_bfloat16 l = __float2bfloat16(wv - __bfloat162float(h));
        uint32_t byte = (uint32_t)(n * 128 + k * 2);
        uint32_t sw = SMEM_SWIZZLE_128B(byte);
        *(__nv_bfloat16*)(smc + S0_WHI + sw) = h;
        *(__nv_bfloat16*)(smc + S0_WLO + sw) = l;
    }
    if (tid < 192) {
        int c = tid >> 6, n = tid & 63;
        Wxyz[c * 64 + n] = W0[n * CIN0 + 64 + c];
    }

    // Gather: 2 threads per row; half0 -> k 0..31, half1 -> k 32..63 + xyz
    int row0 = blockIdx.x * 128;
    {
        int row  = tid >> 1, half = tid & 1;
        int R   = row0 + row;
        int b   = R >> 15;
        int n2  = (R >> 5) & (N2_ - 1);
        int idx = nbr[R];
        const float4* src = (const float4*)(g_xallT + (size_t)(b * N1_ + idx) * CPAD);
        int q0 = half * 8;
#pragma unroll
        for (int q = 0; q < 8; q++) {
            float4 v = src[q0 + q];
            int c = (q0 + q) * 4;
            uint2 ph, pl;
            split2(v.x, v.y, ph.x, pl.x);
            split2(v.z, v.w, ph.y, pl.y);
            uint32_t byte = (uint32_t)(row * 128 + c * 2);
            uint32_t sw = SMEM_SWIZZLE_128B(byte);
            *(uint2*)(smc + S0_XHI + sw) = ph;
            *(uint2*)(smc + S0_XLO + sw) = pl;
        }
        if (half) {
            float4 v = src[16];
            const float4 oz = *(const float4*)(g_oxyz + (size_t)(b * N2_ + n2) * 4);
            XYZ[row * 4 + 0] = v.x - oz.x;
            XYZ[row * 4 + 1] = v.y - oz.y;
            XYZ[row * 4 + 2] = v.z - oz.z;
            XYZ[row * 4 + 3] = 0.0f;
        }
    }
    __syncthreads();

    // mainloop: warp wid -> rows [wid*16, +16), full N=64
    uint32_t xhi32 = (uint32_t)__cvta_generic_to_shared(smc + S0_XHI);
    uint32_t xlo32 = (uint32_t)__cvta_generic_to_shared(smc + S0_XLO);
    uint32_t whi32 = (uint32_t)__cvta_generic_to_shared(smc + S0_WHI);
    uint32_t wlo32 = (uint32_t)__cvta_generic_to_shared(smc + S0_WLO);

    int g  = lane >> 2;
    int rbase = wid * 16;
    int rowA   = rbase + (lane & 15);
    int colAof = (lane >> 4) << 3;
    int rowB7  = (lane & 7) + (((lane >> 4) & 1) << 3);
    int colBof = ((lane >> 3) & 1) << 3;

    float acc[8][4];
#pragma unroll
    for (int n = 0; n < 8; n++)
#pragma unroll
        for (int j = 0; j < 4; j++) acc[n][j] = 0.0f;

#pragma unroll
    for (int kk = 0; kk < 64; kk += 16) {
        uint32_t ahi[4], alo[4];
        ldsm_x4(ahi, sw_off(xhi32, rowA, kk + colAof));
        ldsm_x4(alo, sw_off(xlo32, rowA, kk + colAof));
#pragma unroll
        for (int ntp = 0; ntp < 4; ntp++) {
            uint32_t bh[4], bl[4];
            int rb = ntp * 16 + rowB7;
            ldsm_x4(bh, sw_off(whi32, rb, kk + colBof));
            ldsm_x4(bl, sw_off(wlo32, rb, kk + colBof));
            mma_bf16(acc[2 * ntp],     ahi, bh);
            mma_bf16(acc[2 * ntp],     ahi, bl);
            mma_bf16(acc[2 * ntp],     alo, bh);
            mma_bf16(acc[2 * ntp + 1], ahi, bh + 2);
            mma_bf16(acc[2 * ntp + 1], ahi, bl + 2);
            mma_bf16(acc[2 * ntp + 1], alo, bh + 2);
        }
    }

    // exact fp32 xyz contribution on fragments
    {
        int cq = (lane & 3) * 2;
        float x0[3], x1[3];
#pragma unroll
        for (int ch = 0; ch < 3; ch++) {
            x0[ch] = XYZ[(rbase + g) * 4 + ch];
            x1[ch] = XYZ[(rbase + g + 8) * 4 + ch];
        }
#pragma unroll
        for (int nt = 0; nt < 8; nt++) {
            int c = nt * 8 + cq;
#pragma unroll
            for (int ch = 0; ch < 3; ch++) {
                float w0 = Wxyz[ch * 64 + c], w1 = Wxyz[ch * 64 + c + 1];
                acc[nt][0] = fmaf(x0[ch], w0, acc[nt][0]);
                acc[nt][1] = fmaf(x0[ch], w1, acc[nt][1]);
                acc[nt][2] = fmaf(x1[ch], w0, acc[nt][2]);
                acc[nt][3] = fmaf(x1[ch], w1, acc[nt][3]);
            }
        }
    }

    // stage raw y0 into smem [128][64] (reuses Xhi/Xlo, 32KB)
    __syncthreads();
    float* ystage = (float*)(smc + S0_XHI);
    {
        int cq = (lane & 3) * 2;
#pragma unroll
        for (int nt = 0; nt < 8; nt++) {
            *(float2*)(ystage + (rbase + g)     * 64 + nt * 8 + cq) = make_float2(acc[nt][0], acc[nt][1]);
            *(float2*)(ystage + (rbase + g + 8) * 64 + nt * 8 + cq) = make_float2(acc[nt][2], acc[nt][3]);
        }
    }
    __syncthreads();

    {
        float* dst = g_y0 + (size_t)blockIdx.x * 128 * 64;
#pragma unroll
        for (int q = 0; q < 8; q++) {
            int f = q * 256 + tid;
            *(float4*)(dst + f * 4) = *(const float4*)(ystage + f * 4);
        }
    }

    float* redS = (float*)(smc + S0_WHI);
    float* redQ = redS + 256;
    {
        int col = tid & 63, grp = tid >> 6;
        float s = 0.f, q = 0.f;
        for (int r = grp * 32; r < grp * 32 + 32; r++) {
            float v = ystage[r * 64 + col];
            s += v; q += v * v;
        }
        redS[grp * 64 + col] = s;
        redQ[grp * 64 + col] = q;
    }
    __syncthreads();
    if (tid < 128) {
        int which = tid >> 6, c = tid & 63;
        const float* src = which ? redQ : redS;
        float s = src[c] + src[64 + c] + src[128 + c] + src[192 + c];
        g_part0[(size_t)which * NBT * C0 + (size_t)blockIdx.x * C0 + c] = s;
    }
}

// ---------------------------------------------------------------------------
// GEMM1 (mma.sync + ldmatrix): y1 = relu(bn0(y0)) @ W1^T
// smem: scb/shb 1KB | Xhi 16K | Xlo 16K | Whi 8K | Wlo 8K = 50176 B
// ---------------------------------------------------------------------------
#define T1_SCB  0
#define T1_SHB  512
#define T1_XHI  1024
#define T1_XLO  17408
#define T1_WHI  33792
#define T1_WLO  41984
#define T1_SMEM 50176

__global__ __launch_bounds__(256, 3) void gemm1t_kernel(const float* __restrict__ W1) {
    extern __shared__ char smc[];
    float* scb = (float*)(smc + T1_SCB);
    float* shb = (float*)(smc + T1_SHB);
    int tid = threadIdx.x;
    int wid = tid >> 5, lane = tid & 31;

    if (tid < 64) { scb[tid] = g_scale0[tid]; shb[tid] = g_shift0[tid]; }
    __syncthreads();

    for (int e = tid; e < 64 * 64; e += 256) {
        int n = e >> 6, k = e & 63;
        float wv = W1[e];
        __nv_bfloat16 h = __float2bfloat16(wv);
        __nv_bfloat16 l = __float2bfloat16(wv - __bfloat162float(h));
        uint32_t byte = (uint32_t)(n * 128 + k * 2);
        uint32_t sw = SMEM_SWIZZLE_128B(byte);
        *(__nv_bfloat16*)(smc + T1_WHI + sw) = h;
        *(__nv_bfloat16*)(smc + T1_WLO + sw) = l;
    }

    {
        const char* ytile = (const char*)(g_y0 + (size_t)blockIdx.x * 128 * 64);
#pragma unroll
        for (int q = 0; q < 8; q++) {
            int bo = wid * 4096 + q * 512 + lane * 16;
            float4 v = *(const float4*)(ytile + bo);
            int r = bo >> 8;
            int c = (bo & 255) >> 2;
            float x0 = fmaxf(0.f, fmaf(v.x, scb[c + 0], shb[c + 0]));
            float x1 = fmaxf(0.f, fmaf(v.y, scb[c + 1], shb[c + 1]));
            float x2 = fmaxf(0.f, fmaf(v.z, scb[c + 2], shb[c + 2]));
            float x3 = fmaxf(0.f, fmaf(v.w, scb[c + 3], shb[c + 3]));
            uint2 ph, pl;
            split2(x0, x1, ph.x, pl.x);
            split2(x2, x3, ph.y, pl.y);
            uint32_t byte = (uint32_t)(r * 128 + c * 2);
            uint32_t sw = SMEM_SWIZZLE_128B(byte);
            *(uint2*)(smc + T1_XHI + sw) = ph;
            *(uint2*)(smc + T1_XLO + sw) = pl;
        }
    }
    __syncthreads();

    uint32_t xhi32 = (uint32_t)__cvta_generic_to_shared(smc + T1_XHI);
    uint32_t xlo32 = (uint32_t)__cvta_generic_to_shared(smc + T1_XLO);
    uint32_t whi32 = (uint32_t)__cvta_generic_to_shared(smc + T1_WHI);
    uint32_t wlo32 = (uint32_t)__cvta_generic_to_shared(smc + T1_WLO);

    int g  = lane >> 2;
    int rbase = wid * 16;
    int rowA   = rbase + (lane & 15);
    int colAof = (lane >> 4) << 3;
    int rowB7  = (lane & 7) + (((lane >> 4) & 1) << 3);
    int colBof = ((lane >> 3) & 1) << 3;

    float acc[8][4];
#pragma unroll
    for (int n = 0; n < 8; n++)
#pragma unroll
        for (int j = 0; j < 4; j++) acc[n][j] = 0.0f;

#pragma unroll
    for (int kk = 0; kk < 64; kk += 16) {
        uint32_t ahi[4], alo[4];
        ldsm_x4(ahi, sw_off(xhi32, rowA, kk + colAof));
        ldsm_x4(alo, sw_off(xlo32, rowA, kk + colAof));
#pragma unroll
        for (int ntp = 0; ntp < 4; ntp++) {
            uint32_t bh[4], bl[4];
            int rb = ntp * 16 + rowB7;
            ldsm_x4(bh, sw_off(whi32, rb, kk + colBof));
            ldsm_x4(bl, sw_off(wlo32, rb, kk + colBof));
            mma_bf16(acc[2 * ntp],     ahi, bh);
            mma_bf16(acc[2 * ntp],     ahi, bl);
            mma_bf16(acc[2 * ntp],     alo, bh);
            mma_bf16(acc[2 * ntp + 1], ahi, bh + 2);
            mma_bf16(acc[2 * ntp + 1], ahi, bl + 2);
            mma_bf16(acc[2 * ntp + 1], alo, bh + 2);
        }
    }

    __syncthreads();
    float* ystage = (float*)(smc + T1_XHI);
    {
        int cq = (lane & 3) * 2;
#pragma unroll
        for (int nt = 0; nt < 8; nt++) {
            *(float2*)(ystage + (rbase + g)     * 64 + nt * 8 + cq) = make_float2(acc[nt][0], acc[nt][1]);
            *(float2*)(ystage + (rbase + g + 8) * 64 + nt * 8 + cq) = make_float2(acc[nt][2], acc[nt][3]);
        }
    }
    __syncthreads();

    {
        float* dst = g_y1 + (size_t)blockIdx.x * 128 * 64;
#pragma unroll
        for (int q = 0; q < 8; q++) {
            int f = q * 256 + tid;
            *(float4*)(dst + f * 4) = *(const float4*)(ystage + f * 4);
        }
    }

    float* redS = (float*)(smc + T1_WHI);
    float* redQ = redS + 256;
    {
        int col = tid & 63, grp = tid >> 6;
        float s = 0.f, q = 0.f;
        for (int r = grp * 32; r < grp * 32 + 32; r++) {
            float v = ystage[r * 64 + col];
            s += v; q += v * v;
        }
        redS[grp * 64 + col] = s;
        redQ[grp * 64 + col] = q;
    }
    __syncthreads();
    if (tid < 128) {
        int which = tid >> 6, c = tid & 63;
        const float* src = which ? redQ : redS;
        float s = src[c] + src[64 + c] + src[128 + c] + src[192 + c];
        g_part1[(size_t)which * NBT * C1O + (size_t)blockIdx.x * C1O + c] = s;
    }
}

// ---------------------------------------------------------------------------
// GEMM2 (mma.sync + ldmatrix): y2 = relu(bn1(y1)) @ W2^T, N=128, fused epi
// smem: scb/shb 1KB | Xhi 16K | Xlo 16K | Whi 16K | Wlo 16K | red 4K = 70656 B
// ---------------------------------------------------------------------------
#define T2_SCB  0
#define T2_SHB  512
#define T2_XHI  1024
#define T2_XLO  17408
#define T2_WHI  33792
#define T2_WLO  50176
#define T2_RED  66560
#define T2_SMEM 70656

__global__ __launch_bounds__(256, 2) void gemm2t_kernel(const float* __restrict__ W2) {
    extern __shared__ char smc[];
    float* scb = (float*)(smc + T2_SCB);
    float* shb = (float*)(smc + T2_SHB);
    int tid = threadIdx.x;
    int wid = tid >> 5, lane = tid & 31;

    if (tid < 64) { scb[tid] = g_scale1[tid]; shb[tid] = g_shift1[tid]; }
    __syncthreads();

    for (int e = tid; e < 128 * 64; e += 256) {
        int n = e >> 6, k = e & 63;
        float wv = W2[e];
        __nv_bfloat16 h = __float2bfloat16(wv);
        __nv_bfloat16 l = __float2bfloat16(wv - __bfloat162float(h));
        uint32_t byte = (uint32_t)(n * 128 + k * 2);
        uint32_t sw = SMEM_SWIZZLE_128B(byte);
        *(__nv_bfloat16*)(smc + T2_WHI + sw) = h;
        *(__nv_bfloat16*)(smc + T2_WLO + sw) = l;
    }

    {
        const char* ytile = (const char*)(g_y1 + (size_t)blockIdx.x * 128 * 64);
#pragma unroll
        for (int q = 0; q < 8; q++) {
            int bo = wid * 4096 + q * 512 + lane * 16;
            float4 v = *(const float4*)(ytile + bo);
            int r = bo >> 8;
            int c = (bo & 255) >> 2;
            float x0 = fmaxf(0.f, fmaf(v.x, scb[c + 0], shb[c + 0]));
            float x1 = fmaxf(0.f, fmaf(v.y, scb[c + 1], shb[c + 1]));
            float x2 = fmaxf(0.f, fmaf(v.z, scb[c + 2], shb[c + 2]));
            float x3 = fmaxf(0.f, fmaf(v.w, scb[c + 3], shb[c + 3]));
            uint2 ph, pl;
            split2(x0, x1, ph.x, pl.x);
            split2(x2, x3, ph.y, pl.y);
            uint32_t byte = (uint32_t)(r * 128 + c * 2);
            uint32_t sw = SMEM_SWIZZLE_128B(byte);
            *(uint2*)(smc + T2_XHI + sw) = ph;
            *(uint2*)(smc + T2_XLO + sw) = pl;
        }
    }
    __syncthreads();

    uint32_t xhi32 = (uint32_t)__cvta_generic_to_shared(smc + T2_XHI);
    uint32_t xlo32 = (uint32_t)__cvta_generic_to_shared(smc + T2_XLO);
    uint32_t whi32 = (uint32_t)__cvta_generic_to_shared(smc + T2_WHI);
    uint32_t wlo32 = (uint32_t)__cvta_generic_to_shared(smc + T2_WLO);

    // 8 warps = 4 (M) x 2 (N): rows mw*32..+31, cols nw*64..+63
    int mw = wid & 3, nw = wid >> 2;
    int g  = lane >> 2;
    int rowA0  = mw * 32 + (lane & 15);
    int colAof = (lane >> 4) << 3;
    int rowB7  = (lane & 7) + (((lane >> 4) & 1) << 3);
    int colBof = ((lane >> 3) & 1) << 3;

    float acc[2][8][4];
#pragma unroll
    for (int mt = 0; mt < 2; mt++)
#pragma unroll
        for (int n = 0; n < 8; n++)
#pragma unroll
            for (int j = 0; j < 4; j++) acc[mt][n][j] = 0.0f;

#pragma unroll
    for (int kk = 0; kk < 64; kk += 16) {
        uint32_t ah0[4], al0[4], ah1[4], al1[4];
        ldsm_x4(ah0, sw_off(xhi32, rowA0,      kk + colAof));
        ldsm_x4(al0, sw_off(xlo32, rowA0,      kk + colAof));
        ldsm_x4(ah1, sw_off(xhi32, rowA0 + 16, kk + colAof));
        ldsm_x4(al1, sw_off(xlo32, rowA0 + 16, kk + colAof));
#pragma unroll
        for (int ntp = 0; ntp < 4; ntp++) {
            uint32_t bh[4], bl[4];
            int rb = nw * 64 + ntp * 16 + rowB7;
            ldsm_x4(bh, sw_off(whi32, rb, kk + colBof));
            ldsm_x4(bl, sw_off(wlo32, rb, kk + colBof));
            mma_bf16(acc[0][2 * ntp],     ah0, bh);
            mma_bf16(acc[0][2 * ntp],     ah0, bl);
            mma_bf16(acc[0][2 * ntp],     al0, bh);
            mma_bf16(acc[0][2 * ntp + 1], ah0, bh + 2);
            mma_bf16(acc[0][2 * ntp + 1], ah0, bl + 2);
            mma_bf16(acc[0][2 * ntp + 1], al0, bh + 2);
            mma_bf16(acc[1][2 * ntp],     ah1, bh);
            mma_bf16(acc[1][2 * ntp],     ah1, bl);
            mma_bf16(acc[1][2 * ntp],     al1, bh);
            mma_bf16(acc[1][2 * ntp + 1], ah1, bh + 2);
            mma_bf16(acc[1][2 * ntp + 1], ah1, bl + 2);
            mma_bf16(acc[1][2 * ntp + 1], al1, bh + 2);
        }
    }

    __syncthreads();
    float* ystage = (float*)(smc + T2_XHI);
    {
        int cq = (lane & 3) * 2;
#pragma unroll
        for (int mt = 0; mt < 2; mt++) {
            int rb = mw * 32 + mt * 16;
#pragma unroll
            for (int nt = 0; nt < 8; nt++) {
                int col = nw * 64 + nt * 8 + cq;
                *(float2*)(ystage + (rb + g)     * 128 + col) = make_float2(acc[mt][nt][0], acc[mt][nt][1]);
                *(float2*)(ystage + (rb + g + 8) * 128 + col) = make_float2(acc[mt][nt][2], acc[mt][nt][3]);
            }
        }
    }
    __syncthreads();

    float* redS = (float*)(smc + T2_RED);
    float* redQ = redS + 512;
    {
        int row0 = blockIdx.x * 128;
        int b   = row0 >> 15;
        int n2b = (row0 >> 5) & (N2_ - 1);
        int col = tid & 127;
#pragma unroll
        for (int gi = 0; gi < 2; gi++) {
            int grp = ((tid >> 7) << 1) + gi;
            float v0 = ystage[(grp * 32) * 128 + col];
            float s = 0.f, q = 0.f, mx = v0, mn = v0;
            for (int r = grp * 32; r < grp * 32 + 32; r++) {
                float v = ystage[r * 128 + col];
                s += v; q += v * v;
                mx = fmaxf(mx, v); mn = fminf(mn, v);
            }
            redS[grp * 128 + col] = s;
            redQ[grp * 128 + col] = q;
            size_t o = (size_t)(b * N2_ + n2b + grp) * C2 + col;
            g_max2[o] = mx;
            g_min2[o] = mn;
        }
    }
    __syncthreads();
    {
        int which = tid >> 7, c = tid & 127;
        const float* src = which ? redQ : redS;
        float s = src[c] + src[128 + c] + src[256 + c] + src[384 + c];
        g_part2[(size_t)which * NBT * C2 + (size_t)blockIdx.x * C2 + c] = s;
    }
}

// ---------------------------------------------------------------------------
// Stats finalize
// ---------------------------------------------------------------------------
__global__ void stats_kernel(int layer, const float* __restrict__ gamma,
                             const float* __restrict__ beta) {
    const float* part; int nb, C; float* scale; float* shift;
    if (layer == 0)      { part = g_part0; nb = NBT; C = C0;  scale = g_scale0; shift = g_shift0; }
    else if (layer == 1) { part = g_part1; nb = NBT; C = C1O; scale = g_scale1; shift = g_shift1; }
    else                 { part = g_part2; nb = NBT; C = C2;  scale = g_scale2; shift = g_shift2; }

    __shared__ float shs[256], shq[256];
    int c = blockIdx.x;
    int tid = threadIdx.x;
    float s = 0.0f, q = 0.0f;
    for (int i = tid; i < nb; i += 256) {
        s += part[(size_t)i * C + c];
        q += part[(size_t)(nb + i) * C + c];
    }
    shs[tid] = s; shq[tid] = q;
    __syncthreads();
    for (int off = 128; off > 0; off >>= 1) {
        if (tid < off) { shs[tid] += shs[tid + off]; shq[tid] += shq[tid + off]; }
        __syncthreads();
    }
    if (tid == 0) {
        float mean = shs[0] / CNT_;
        float var  = shq[0] / CNT_ - mean * mean;
        float sc   = gamma[c] * rsqrtf(var + EPS_);
        scale[c] = sc;
        shift[c] = beta[c] - mean * sc;
    }
}

// ---------------------------------------------------------------------------
// Final output
// ---------------------------------------------------------------------------
__global__ void final_kernel(float* __restrict__ out) {
    int o = blockIdx.x * 256 + threadIdx.x;
    if (o >= B_ * C2 * N2_) return;
    int n2 = o & (N2_ - 1);
    int c  = (o >> 10) & (C2 - 1);
    int b  = o >> 17;
    float sc = g_scale2[c], sh = g_shift2[c];
    size_t mi = (size_t)(b * N2_ + n2) * C2 + c;
    float v = (sc >= 0.0f) ? g_max2[mi] : g_min2[mi];
    out[o] = fmaxf(0.0f, fmaf(sc, v, sh));
}

// ---------------------------------------------------------------------------
// Launcher
// ---------------------------------------------------------------------------
extern "C" void kernel_launch(void* const* d_in, const int* in_sizes, int n_in,
                              void* d_out, int out_size) {
    const float* in_xyz     = (const float*)d_in[0];
    const float* out_xyz    = (const float*)d_in[1];
    const float* in_feature = (const float*)d_in[2];
    const int*   nbr        = (const int*)  d_in[3];
    const float* W0 = (const float*)d_in[4];
    const float* g0 = (const float*)d_in[5];
    const float* b0 = (const float*)d_in[6];
    const float* W1 = (const float*)d_in[7];
    const float* g1 = (const float*)d_in[8];
    const float* b1 = (const float*)d_in[9];
    const float* W2 = (const float*)d_in[10];
    const float* g2 = (const float*)d_in[11];
    const float* b2 = (const float*)d_in[12];
    float* out = (float*)d_out;

    cudaFuncSetAttribute(gemm0t_kernel, cudaFuncAttributeMaxDynamicSharedMemorySize, S0_SMEM);
    cudaFuncSetAttribute(gemm1t_kernel, cudaFuncAttributeMaxDynamicSharedMemorySize, T1_SMEM);
    cudaFuncSetAttribute(gemm2t_kernel, cudaFuncAttributeMaxDynamicSharedMemorySize, T2_SMEM);

    // launch order keeps gemm2t at index 5 for the fixed ncu -s 5 -c 1 window
    fused_pre_kernel<<<dim3(N1_ / 32 + 1, B_), dim3(32, 8)>>>(in_feature, in_xyz, out_xyz);

    gemm0t_kernel<<<NBT, 256, S0_SMEM>>>(nbr, W0);
    stats_kernel<<<C0, 256>>>(0, g0, b0);

    gemm1t_kernel<<<NBT, 256, T1_SMEM>>>(W1);
    stats_kernel<<<C1O, 256>>>(1, g1, b1);

    gemm2t_kernel<<<NBT, 256, T2_SMEM>>>(W2);
    stats_kernel<<<C2, 256>>>(2, g2, b2);

    final_kernel<<<(B_ * C2 * N2_ + 255) / 256, 256>>>(out);
}

// round 13
// speedup vs baseline: 3.0923x; 1.1514x over previous
#include <cuda_runtime.h>
#include <cuda_bf16.h>
#include <math.h>
#include <cstdint>

// ---------------------------------------------------------------------------
// Problem constants
// ---------------------------------------------------------------------------
#define B_    16
#define N1_   4096
#define N2_   1024
#define KNB   32
#define CIN0  67
#define CPAD  68
#define C0    64
#define C1O   64
#define C2    128
#define M_    (B_ * N2_ * KNB)     // 524288
#define NB0T  (M_ / 256)           // 2048
#define NB1T  (M_ / 256)           // 2048
#define NB2T  (M_ / 128)           // 4096
#define CNT_  524288.0f
#define EPS_  1e-5f

// ---------------------------------------------------------------------------
// mma.sync / ldmatrix helpers (baseline PTX, works on compute_103)
// ---------------------------------------------------------------------------
__device__ __forceinline__ void mma_bf16(float* d, const uint32_t* a, const uint32_t* b) {
    asm volatile(
        "mma.sync.aligned.m16n8k16.row.col.f32.bf16.bf16.f32 "
        "{%0,%1,%2,%3}, {%4,%5,%6,%7}, {%8,%9}, {%0,%1,%2,%3};"
        : "+f"(d[0]), "+f"(d[1]), "+f"(d[2]), "+f"(d[3])
        : "r"(a[0]), "r"(a[1]), "r"(a[2]), "r"(a[3]), "r"(b[0]), "r"(b[1]));
}
__device__ __forceinline__ void ldsm_x4(uint32_t* r, uint32_t addr) {
    asm volatile("ldmatrix.sync.aligned.m8n8.x4.shared.b16 {%0,%1,%2,%3}, [%4];"
        : "=r"(r[0]), "=r"(r[1]), "=r"(r[2]), "=r"(r[3]) : "r"(addr));
}
// swizzled smem address for bf16 tiles with 128-byte rows (64 bf16/row)
__device__ __forceinline__ uint32_t sw_off(uint32_t base32, int row, int col) {
    uint32_t byte = (uint32_t)(row * 128 + col * 2);
    byte ^= (byte >> 3) & 0x70;
    return base32 + byte;
}
#define SMEM_SWIZZLE_128B(b) ((b) ^ (((b) >> 3) & 0x70))

// bf16 hi/lo split of two fp32 values, packed as bf16x2 words
__device__ __forceinline__ void split2(float a, float b, uint32_t& hi, uint32_t& lo) {
    __nv_bfloat16 ha = __float2bfloat16(a), hb = __float2bfloat16(b);
    __nv_bfloat16 la = __float2bfloat16(a - __bfloat162float(ha));
    __nv_bfloat16 lb = __float2bfloat16(b - __bfloat162float(hb));
    hi = (uint32_t)__bfloat16_as_ushort(ha) | ((uint32_t)__bfloat16_as_ushort(hb) << 16);
    lo = (uint32_t)__bfloat16_as_ushort(la) | ((uint32_t)__bfloat16_as_ushort(lb) << 16);
}

// butterfly reductions over the g-lanes (lane bits 2..4)
__device__ __forceinline__ float redg_sum(float v) {
    v += __shfl_xor_sync(0xffffffffu, v, 4);
    v += __shfl_xor_sync(0xffffffffu, v, 8);
    v += __shfl_xor_sync(0xffffffffu, v, 16);
    return v;
}
__device__ __forceinline__ float redg_max(float v) {
    v = fmaxf(v, __shfl_xor_sync(0xffffffffu, v, 4));
    v = fmaxf(v, __shfl_xor_sync(0xffffffffu, v, 8));
    v = fmaxf(v, __shfl_xor_sync(0xffffffffu, v, 16));
    return v;
}
__device__ __forceinline__ float redg_min(float v) {
    v = fminf(v, __shfl_xor_sync(0xffffffffu, v, 4));
    v = fminf(v, __shfl_xor_sync(0xffffffffu, v, 8));
    v = fminf(v, __shfl_xor_sync(0xffffffffu, v, 16));
    return v;
}

// ---------------------------------------------------------------------------
// Scratch
// ---------------------------------------------------------------------------
__device__ float g_xallT[B_ * N1_ * CPAD];
__device__ float g_oxyz [B_ * N2_ * 4];
__device__ float g_y0[(size_t)M_ * C0];
__device__ float g_y1[(size_t)M_ * C1O];
__device__ float g_part0[2 * NB0T * C0];
__device__ float g_part1[2 * NB1T * C1O];
__device__ float g_part2[2 * NB2T * C2];
__device__ float g_scale0[C0],  g_shift0[C0];
__device__ float g_scale1[C1O], g_shift1[C1O];
__device__ float g_scale2[C2],  g_shift2[C2];
__device__ float g_max2[B_ * N2_ * C2];
__device__ float g_min2[B_ * N2_ * C2];

// ---------------------------------------------------------------------------
// Fused pre: transpose feat+xyz -> [B][N1][68], plus oxyz pack
// ---------------------------------------------------------------------------
__global__ void fused_pre_kernel(const float* __restrict__ in_feature,
                                 const float* __restrict__ in_xyz,
                                 const float* __restrict__ out_xyz) {
    int b  = blockIdx.y;
    int tx = threadIdx.x;
    int ty = threadIdx.y;
    int tid = ty * 32 + tx;

    if (blockIdx.x == N1_ / 32) {
        for (int n2 = tid; n2 < N2_; n2 += 256) {
            int i = b * N2_ + n2;
            g_oxyz[i * 4 + 0] = out_xyz[(b * 3 + 0) * N2_ + n2];
            g_oxyz[i * 4 + 1] = out_xyz[(b * 3 + 1) * N2_ + n2];
            g_oxyz[i * 4 + 2] = out_xyz[(b * 3 + 2) * N2_ + n2];
            g_oxyz[i * 4 + 3] = 0.0f;
        }
        return;
    }

    __shared__ float tile[CPAD][33];
    int n0 = blockIdx.x * 32;
    for (int c = ty; c < CPAD; c += 8) {
        float v;
        if (c < 64)      v = in_feature[((size_t)b * 64 + c) * N1_ + n0 + tx];
        else if (c < 67) v = in_xyz[((size_t)b * 3 + (c - 64)) * N1_ + n0 + tx];
        else             v = 0.0f;
        tile[c][tx] = v;
    }
    __syncthreads();
    for (int e = tid; e < 32 * CPAD; e += 256) {
        int nl = e / CPAD;
        int c  = e % CPAD;
        g_xallT[((size_t)(b * N1_ + n0 + nl)) * CPAD + c] = tile[c][nl];
    }
}

// ---------------------------------------------------------------------------
// GEMM0: gather -> y0 = X(67ch) @ W0^T.  256-row tiles.
// feature 64ch via bf16 split MMA; xyz 3ch via exact fp32 FFMA on fragments.
// smem: XYZ 4K | Wxyz 1K | Xhi 32K | Xlo 32K | Whi 8K | Wlo 8K = 87040 B
// ---------------------------------------------------------------------------
#define S0_XYZ   0
#define S0_WXYZ  4096
#define S0_XHI   5120
#define S0_XLO   37888
#define S0_WHI   70656
#define S0_WLO   78848
#define S0_SMEM  87040

__global__ __launch_bounds__(256, 2) void gemm0t_kernel(const int* __restrict__ nbr,
                                                        const float* __restrict__ W0) {
    extern __shared__ char smc[];
    float* XYZ  = (float*)(smc + S0_XYZ);    // [256][4]
    float* Wxyz = (float*)(smc + S0_WXYZ);   // [3][64]
    int tid = threadIdx.x;
    int wid = tid >> 5, lane = tid & 31;

    // W0 feature part [64 cout][64 cin] -> Whi/Wlo swizzled
    for (int e = tid; e < 64 * 64; e += 256) {
        int n = e >> 6, k = e & 63;
        float wv = W0[n * CIN0 + k];
        __nv_bfloat16 h = __float2bfloat16(wv);
        __nv_bfloat16 l = __float2bfloat16(wv - __bfloat162float(h));
        uint32_t byte = (uint32_t)(n * 128 + k * 2);
        uint32_t sw = SMEM_SWIZZLE_128B(byte);
        *(__nv_bfloat16*)(smc + S0_WHI + sw) = h;
        *(__nv_bfloat16*)(smc + S0_WLO + sw) = l;
    }
    if (tid < 192) {
        int c = tid >> 6, n = tid & 63;
        Wxyz[c * 64 + n] = W0[n * CIN0 + 64 + c];
    }

    // Gather: one thread per row (256 rows)
    int row0 = blockIdx.x * 256;
    {
        int R   = row0 + tid;
        int b   = R >> 15;
        int n2  = (R >> 5) & (N2_ - 1);
        int idx = nbr[R];
        const float4* src = (const float4*)(g_xallT + (size_t)(b * N1_ + idx) * CPAD);
#pragma unroll
        for (int q = 0; q < 16; q++) {
            float4 v = src[q];
            int c = q * 4;
            uint2 ph, pl;
            split2(v.x, v.y, ph.x, pl.x);
            split2(v.z, v.w, ph.y, pl.y);
            uint32_t byte = (uint32_t)(tid * 128 + c * 2);
            uint32_t sw = SMEM_SWIZZLE_128B(byte);
            *(uint2*)(smc + S0_XHI + sw) = ph;
            *(uint2*)(smc + S0_XLO + sw) = pl;
        }
        {
            float4 v = src[16];
            const float4 oz = *(const float4*)(g_oxyz + (size_t)(b * N2_ + n2) * 4);
            XYZ[tid * 4 + 0] = v.x - oz.x;
            XYZ[tid * 4 + 1] = v.y - oz.y;
            XYZ[tid * 4 + 2] = v.z - oz.z;
            XYZ[tid * 4 + 3] = 0.0f;
        }
    }
    __syncthreads();

    // mainloop: warp wid -> rows [wid*32, +32), full N=64
    uint32_t xhi32 = (uint32_t)__cvta_generic_to_shared(smc + S0_XHI);
    uint32_t xlo32 = (uint32_t)__cvta_generic_to_shared(smc + S0_XLO);
    uint32_t whi32 = (uint32_t)__cvta_generic_to_shared(smc + S0_WHI);
    uint32_t wlo32 = (uint32_t)__cvta_generic_to_shared(smc + S0_WLO);

    int g  = lane >> 2;
    int cq = (lane & 3) * 2;
    int rbase  = wid * 32;
    int rowA0  = rbase + (lane & 15);
    int colAof = (lane >> 4) << 3;
    int rowB7  = (lane & 7) + (((lane >> 4) & 1) << 3);
    int colBof = ((lane >> 3) & 1) << 3;

    float acc[2][8][4];
#pragma unroll
    for (int mt = 0; mt < 2; mt++)
#pragma unroll
        for (int n = 0; n < 8; n++)
#pragma unroll
            for (int j = 0; j < 4; j++) acc[mt][n][j] = 0.0f;

#pragma unroll
    for (int kk = 0; kk < 64; kk += 16) {
        uint32_t ah0[4], al0[4], ah1[4], al1[4];
        ldsm_x4(ah0, sw_off(xhi32, rowA0,      kk + colAof));
        ldsm_x4(al0, sw_off(xlo32, rowA0,      kk + colAof));
        ldsm_x4(ah1, sw_off(xhi32, rowA0 + 16, kk + colAof));
        ldsm_x4(al1, sw_off(xlo32, rowA0 + 16, kk + colAof));
#pragma unroll
        for (int ntp = 0; ntp < 4; ntp++) {
            uint32_t bh[4], bl[4];
            int rb = ntp * 16 + rowB7;
            ldsm_x4(bh, sw_off(whi32, rb, kk + colBof));
            ldsm_x4(bl, sw_off(wlo32, rb, kk + colBof));
            mma_bf16(acc[0][2 * ntp],     ah0, bh);
            mma_bf16(acc[0][2 * ntp],     ah0, bl);
            mma_bf16(acc[0][2 * ntp],     al0, bh);
            mma_bf16(acc[0][2 * ntp + 1], ah0, bh + 2);
            mma_bf16(acc[0][2 * ntp + 1], ah0, bl + 2);
            mma_bf16(acc[0][2 * ntp + 1], al0, bh + 2);
            mma_bf16(acc[1][2 * ntp],     ah1, bh);
            mma_bf16(acc[1][2 * ntp],     ah1, bl);
            mma_bf16(acc[1][2 * ntp],     al1, bh);
            mma_bf16(acc[1][2 * ntp + 1], ah1, bh + 2);
            mma_bf16(acc[1][2 * ntp + 1], ah1, bl + 2);
            mma_bf16(acc[1][2 * ntp + 1], al1, bh + 2);
        }
    }

    // exact fp32 xyz contribution on fragments
    {
        float xr[2][2][3];
#pragma unroll
        for (int mt = 0; mt < 2; mt++)
#pragma unroll
            for (int ch = 0; ch < 3; ch++) {
                xr[mt][0][ch] = XYZ[(rbase + mt * 16 + g) * 4 + ch];
                xr[mt][1][ch] = XYZ[(rbase + mt * 16 + g + 8) * 4 + ch];
            }
#pragma unroll
        for (int nt = 0; nt < 8; nt++) {
            int c = nt * 8 + cq;
#pragma unroll
            for (int ch = 0; ch < 3; ch++) {
                float w0 = Wxyz[ch * 64 + c], w1 = Wxyz[ch * 64 + c + 1];
#pragma unroll
                for (int mt = 0; mt < 2; mt++) {
                    acc[mt][nt][0] = fmaf(xr[mt][0][ch], w0, acc[mt][nt][0]);
                    acc[mt][nt][1] = fmaf(xr[mt][0][ch], w1, acc[mt][nt][1]);
                    acc[mt][nt][2] = fmaf(xr[mt][1][ch], w0, acc[mt][nt][2]);
                    acc[mt][nt][3] = fmaf(xr[mt][1][ch], w1, acc[mt][nt][3]);
                }
            }
        }
    }

    // direct global write of y0 (float2, full 32B sectors)
    {
        float* dst = g_y0 + (size_t)blockIdx.x * 256 * 64;
#pragma unroll
        for (int mt = 0; mt < 2; mt++) {
            int r0 = rbase + mt * 16 + g;
#pragma unroll
            for (int nt = 0; nt < 8; nt++) {
                int c = nt * 8 + cq;
                *(float2*)(dst + (size_t)r0 * 64 + c)       = make_float2(acc[mt][nt][0], acc[mt][nt][1]);
                *(float2*)(dst + (size_t)(r0 + 8) * 64 + c) = make_float2(acc[mt][nt][2], acc[mt][nt][3]);
            }
        }
    }

    // stats partials via butterfly over g-lanes
    __syncthreads();                       // done reading W region
    float* redS = (float*)(smc + S0_WHI);  // [8][64]
    float* redQ = redS + 512;
#pragma unroll
    for (int nt = 0; nt < 8; nt++) {
        float a00 = acc[0][nt][0], a01 = acc[0][nt][1], a02 = acc[0][nt][2], a03 = acc[0][nt][3];
        float a10 = acc[1][nt][0], a11 = acc[1][nt][1], a12 = acc[1][nt][2], a13 = acc[1][nt][3];
        float s0 = a00 + a02 + a10 + a12;
        float s1 = a01 + a03 + a11 + a13;
        float q0 = a00 * a00 + a02 * a02 + a10 * a10 + a12 * a12;
        float q1 = a01 * a01 + a03 * a03 + a11 * a11 + a13 * a13;
        s0 = redg_sum(s0); s1 = redg_sum(s1);
        q0 = redg_sum(q0); q1 = redg_sum(q1);
        if (lane < 4) {
            redS[wid * 64 + nt * 8 + cq]     = s0;
            redS[wid * 64 + nt * 8 + cq + 1] = s1;
            redQ[wid * 64 + nt * 8 + cq]     = q0;
            redQ[wid * 64 + nt * 8 + cq + 1] = q1;
        }
    }
    __syncthreads();
    if (tid < 128) {
        int which = tid >> 6, c = tid & 63;
        const float* src = which ? redQ : redS;
        float s = 0.0f;
#pragma unroll
        for (int w = 0; w < 8; w++) s += src[w * 64 + c];
        g_part0[(size_t)which * NB0T * C0 + (size_t)blockIdx.x * C0 + c] = s;
    }
}

// ---------------------------------------------------------------------------
// GEMM1: y1 = relu(bn0(y0)) @ W1^T.  256-row tiles.
// smem: scb/shb | Xhi 32K | Xlo 32K | Whi 8K | Wlo 8K = 82944 B
// ---------------------------------------------------------------------------
#define T1_SCB  0
#define T1_SHB  256
#define T1_XHI  1024
#define T1_XLO  33792
#define T1_WHI  66560
#define T1_WLO  74752
#define T1_SMEM 82944

__global__ __launch_bounds__(256, 2) void gemm1t_kernel(const float* __restrict__ W1) {
    extern __shared__ char smc[];
    float* scb = (float*)(smc + T1_SCB);
    float* shb = (float*)(smc + T1_SHB);
    int tid = threadIdx.x;
    int wid = tid >> 5, lane = tid & 31;

    if (tid < 64) { scb[tid] = g_scale0[tid]; shb[tid] = g_shift0[tid]; }
    __syncthreads();

    for (int e = tid; e < 64 * 64; e += 256) {
        int n = e >> 6, k = e & 63;
        float wv = W1[e];
        __nv_bfloat16 h = __float2bfloat16(wv);
        __nv_bfloat16 l = __float2bfloat16(wv - __bfloat162float(h));
        uint32_t byte = (uint32_t)(n * 128 + k * 2);
        uint32_t sw = SMEM_SWIZZLE_128B(byte);
        *(__nv_bfloat16*)(smc + T1_WHI + sw) = h;
        *(__nv_bfloat16*)(smc + T1_WLO + sw) = l;
    }

    // X tile: 256 rows x 64 cols of relu(bn0(y0)) -> Xhi/Xlo swizzled
    {
        const char* ytile = (const char*)(g_y0 + (size_t)blockIdx.x * 256 * 64);
#pragma unroll
        for (int q = 0; q < 16; q++) {
            int bo = wid * 8192 + q * 512 + lane * 16;
            float4 v = *(const float4*)(ytile + bo);
            int r = bo >> 8;
            int c = (bo & 255) >> 2;
            float x0 = fmaxf(0.f, fmaf(v.x, scb[c + 0], shb[c + 0]));
            float x1 = fmaxf(0.f, fmaf(v.y, scb[c + 1], shb[c + 1]));
            float x2 = fmaxf(0.f, fmaf(v.z, scb[c + 2], shb[c + 2]));
            float x3 = fmaxf(0.f, fmaf(v.w, scb[c + 3], shb[c + 3]));
            uint2 ph, pl;
            split2(x0, x1, ph.x, pl.x);
            split2(x2, x3, ph.y, pl.y);
            uint32_t byte = (uint32_t)(r * 128 + c * 2);
            uint32_t sw = SMEM_SWIZZLE_128B(byte);
            *(uint2*)(smc + T1_XHI + sw) = ph;
            *(uint2*)(smc + T1_XLO + sw) = pl;
        }
    }
    __syncthreads();

    uint32_t xhi32 = (uint32_t)__cvta_generic_to_shared(smc + T1_XHI);
    uint32_t xlo32 = (uint32_t)__cvta_generic_to_shared(smc + T1_XLO);
    uint32_t whi32 = (uint32_t)__cvta_generic_to_shared(smc + T1_WHI);
    uint32_t wlo32 = (uint32_t)__cvta_generic_to_shared(smc + T1_WLO);

    int g  = lane >> 2;
    int cq = (lane & 3) * 2;
    int rbase  = wid * 32;
    int rowA0  = rbase + (lane & 15);
    int colAof = (lane >> 4) << 3;
    int rowB7  = (lane & 7) + (((lane >> 4) & 1) << 3);
    int colBof = ((lane >> 3) & 1) << 3;

    float acc[2][8][4];
#pragma unroll
    for (int mt = 0; mt < 2; mt++)
#pragma unroll
        for (int n = 0; n < 8; n++)
#pragma unroll
            for (int j = 0; j < 4; j++) acc[mt][n][j] = 0.0f;

#pragma unroll
    for (int kk = 0; kk < 64; kk += 16) {
        uint32_t ah0[4], al0[4], ah1[4], al1[4];
        ldsm_x4(ah0, sw_off(xhi32, rowA0,      kk + colAof));
        ldsm_x4(al0, sw_off(xlo32, rowA0,      kk + colAof));
        ldsm_x4(ah1, sw_off(xhi32, rowA0 + 16, kk + colAof));
        ldsm_x4(al1, sw_off(xlo32, rowA0 + 16, kk + colAof));
#pragma unroll
        for (int ntp = 0; ntp < 4; ntp++) {
            uint32_t bh[4], bl[4];
            int rb = ntp * 16 + rowB7;
            ldsm_x4(bh, sw_off(whi32, rb, kk + colBof));
            ldsm_x4(bl, sw_off(wlo32, rb, kk + colBof));
            mma_bf16(acc[0][2 * ntp],     ah0, bh);
            mma_bf16(acc[0][2 * ntp],     ah0, bl);
            mma_bf16(acc[0][2 * ntp],     al0, bh);
            mma_bf16(acc[0][2 * ntp + 1], ah0, bh + 2);
            mma_bf16(acc[0][2 * ntp + 1], ah0, bl + 2);
            mma_bf16(acc[0][2 * ntp + 1], al0, bh + 2);
            mma_bf16(acc[1][2 * ntp],     ah1, bh);
            mma_bf16(acc[1][2 * ntp],     ah1, bl);
            mma_bf16(acc[1][2 * ntp],     al1, bh);
            mma_bf16(acc[1][2 * ntp + 1], ah1, bh + 2);
            mma_bf16(acc[1][2 * ntp + 1], ah1, bl + 2);
            mma_bf16(acc[1][2 * ntp + 1], al1, bh + 2);
        }
    }

    // direct global write of y1
    {
        float* dst = g_y1 + (size_t)blockIdx.x * 256 * 64;
#pragma unroll
        for (int mt = 0; mt < 2; mt++) {
            int r0 = rbase + mt * 16 + g;
#pragma unroll
            for (int nt = 0; nt < 8; nt++) {
                int c = nt * 8 + cq;
                *(float2*)(dst + (size_t)r0 * 64 + c)       = make_float2(acc[mt][nt][0], acc[mt][nt][1]);
                *(float2*)(dst + (size_t)(r0 + 8) * 64 + c) = make_float2(acc[mt][nt][2], acc[mt][nt][3]);
            }
        }
    }

    // stats partials via butterfly
    __syncthreads();
    float* redS = (float*)(smc + T1_WHI);
    float* redQ = redS + 512;
#pragma unroll
    for (int nt = 0; nt < 8; nt++) {
        float a00 = acc[0][nt][0], a01 = acc[0][nt][1], a02 = acc[0][nt][2], a03 = acc[0][nt][3];
        float a10 = acc[1][nt][0], a11 = acc[1][nt][1], a12 = acc[1][nt][2], a13 = acc[1][nt][3];
        float s0 = a00 + a02 + a10 + a12;
        float s1 = a01 + a03 + a11 + a13;
        float q0 = a00 * a00 + a02 * a02 + a10 * a10 + a12 * a12;
        float q1 = a01 * a01 + a03 * a03 + a11 * a11 + a13 * a13;
        s0 = redg_sum(s0); s1 = redg_sum(s1);
        q0 = redg_sum(q0); q1 = redg_sum(q1);
        if (lane < 4) {
            redS[wid * 64 + nt * 8 + cq]     = s0;
            redS[wid * 64 + nt * 8 + cq + 1] = s1;
            redQ[wid * 64 + nt * 8 + cq]     = q0;
            redQ[wid * 64 + nt * 8 + cq + 1] = q1;
        }
    }
    __syncthreads();
    if (tid < 128) {
        int which = tid >> 6, c = tid & 63;
        const float* src = which ? redQ : redS;
        float s = 0.0f;
#pragma unroll
        for (int w = 0; w < 8; w++) s += src[w * 64 + c];
        g_part1[(size_t)which * NB1T * C1O + (size_t)blockIdx.x * C1O + c] = s;
    }
}

// ---------------------------------------------------------------------------
// GEMM2: y2 = relu(bn1(y1)) @ W2^T, N=128, 128-row tiles.
// Epilogue entirely register-resident: shuffle max/min per K-group + stats.
// smem: scb/shb | Xhi 16K | Xlo 16K | Whi 16K | Wlo 16K | red 4K = 70656 B
// ---------------------------------------------------------------------------
#define T2_SCB  0
#define T2_SHB  256
#define T2_XHI  1024
#define T2_XLO  17408
#define T2_WHI  33792
#define T2_WLO  50176
#define T2_RED  66560
#define T2_SMEM 70656

__global__ __launch_bounds__(256, 2) void gemm2t_kernel(const float* __restrict__ W2) {
    extern __shared__ char smc[];
    float* scb = (float*)(smc + T2_SCB);
    float* shb = (float*)(smc + T2_SHB);
    int tid = threadIdx.x;
    int wid = tid >> 5, lane = tid & 31;

    if (tid < 64) { scb[tid] = g_scale1[tid]; shb[tid] = g_shift1[tid]; }
    __syncthreads();

    for (int e = tid; e < 128 * 64; e += 256) {
        int n = e >> 6, k = e & 63;
        float wv = W2[e];
        __nv_bfloat16 h = __float2bfloat16(wv);
        __nv_bfloat16 l = __float2bfloat16(wv - __bfloat162float(h));
        uint32_t byte = (uint32_t)(n * 128 + k * 2);
        uint32_t sw = SMEM_SWIZZLE_128B(byte);
        *(__nv_bfloat16*)(smc + T2_WHI + sw) = h;
        *(__nv_bfloat16*)(smc + T2_WLO + sw) = l;
    }

    {
        const char* ytile = (const char*)(g_y1 + (size_t)blockIdx.x * 128 * 64);
#pragma unroll
        for (int q = 0; q < 8; q++) {
            int bo = wid * 4096 + q * 512 + lane * 16;
            float4 v = *(const float4*)(ytile + bo);
            int r = bo >> 8;
            int c = (bo & 255) >> 2;
            float x0 = fmaxf(0.f, fmaf(v.x, scb[c + 0], shb[c + 0]));
            float x1 = fmaxf(0.f, fmaf(v.y, scb[c + 1], shb[c + 1]));
            float x2 = fmaxf(0.f, fmaf(v.z, scb[c + 2], shb[c + 2]));
            float x3 = fmaxf(0.f, fmaf(v.w, scb[c + 3], shb[c + 3]));
            uint2 ph, pl;
            split2(x0, x1, ph.x, pl.x);
            split2(x2, x3, ph.y, pl.y);
            uint32_t byte = (uint32_t)(r * 128 + c * 2);
            uint32_t sw = SMEM_SWIZZLE_128B(byte);
            *(uint2*)(smc + T2_XHI + sw) = ph;
            *(uint2*)(smc + T2_XLO + sw) = pl;
        }
    }
    __syncthreads();

    uint32_t xhi32 = (uint32_t)__cvta_generic_to_shared(smc + T2_XHI);
    uint32_t xlo32 = (uint32_t)__cvta_generic_to_shared(smc + T2_XLO);
    uint32_t whi32 = (uint32_t)__cvta_generic_to_shared(smc + T2_WHI);
    uint32_t wlo32 = (uint32_t)__cvta_generic_to_shared(smc + T2_WLO);

    // 8 warps = 4 (M) x 2 (N): warp covers rows mw*32..+31 (one K-group), cols nw*64..+63
    int mw = wid & 3, nw = wid >> 2;
    int g  = lane >> 2;
    int cq = (lane & 3) * 2;
    int rowA0  = mw * 32 + (lane & 15);
    int colAof = (lane >> 4) << 3;
    int rowB7  = (lane & 7) + (((lane >> 4) & 1) << 3);
    int colBof = ((lane >> 3) & 1) << 3;

    float acc[2][8][4];
#pragma unroll
    for (int mt = 0; mt < 2; mt++)
#pragma unroll
        for (int n = 0; n < 8; n++)
#pragma unroll
            for (int j = 0; j < 4; j++) acc[mt][n][j] = 0.0f;

#pragma unroll
    for (int kk = 0; kk < 64; kk += 16) {
        uint32_t ah0[4], al0[4], ah1[4], al1[4];
        ldsm_x4(ah0, sw_off(xhi32, rowA0,      kk + colAof));
        ldsm_x4(al0, sw_off(xlo32, rowA0,      kk + colAof));
        ldsm_x4(ah1, sw_off(xhi32, rowA0 + 16, kk + colAof));
        ldsm_x4(al1, sw_off(xlo32, rowA0 + 16, kk + colAof));
#pragma unroll
        for (int ntp = 0; ntp < 4; ntp++) {
            uint32_t bh[4], bl[4];
            int rb = nw * 64 + ntp * 16 + rowB7;
            ldsm_x4(bh, sw_off(whi32, rb, kk + colBof));
            ldsm_x4(bl, sw_off(wlo32, rb, kk + colBof));
            mma_bf16(acc[0][2 * ntp],     ah0, bh);
            mma_bf16(acc[0][2 * ntp],     ah0, bl);
            mma_bf16(acc[0][2 * ntp],     al0, bh);
            mma_bf16(acc[0][2 * ntp + 1], ah0, bh + 2);
            mma_bf16(acc[0][2 * ntp + 1], ah0, bl + 2);
            mma_bf16(acc[0][2 * ntp + 1], al0, bh + 2);
            mma_bf16(acc[1][2 * ntp],     ah1, bh);
            mma_bf16(acc[1][2 * ntp],     ah1, bl);
            mma_bf16(acc[1][2 * ntp],     al1, bh);
            mma_bf16(acc[1][2 * ntp + 1], ah1, bh + 2);
            mma_bf16(acc[1][2 * ntp + 1], ah1, bl + 2);
            mma_bf16(acc[1][2 * ntp + 1], al1, bh + 2);
        }
    }

    // register-resident epilogue: the warp's 32 rows == one K-group
    int row0 = blockIdx.x * 128;
    int b_   = row0 >> 15;
    int n2g  = ((row0 >> 5) & (N2_ - 1)) + mw;
    float* redS = (float*)(smc + T2_RED);   // [4 mw][128]
    float* redQ = redS + 512;
    size_t obase = (size_t)(b_ * N2_ + n2g) * C2;

    __syncthreads();   // done reading W/X smem before redS reuse barrier semantics
#pragma unroll
    for (int nt = 0; nt < 8; nt++) {
        float a00 = acc[0][nt][0], a01 = acc[0][nt][1], a02 = acc[0][nt][2], a03 = acc[0][nt][3];
        float a10 = acc[1][nt][0], a11 = acc[1][nt][1], a12 = acc[1][nt][2], a13 = acc[1][nt][3];
        float s0 = a00 + a02 + a10 + a12;
        float s1 = a01 + a03 + a11 + a13;
        float q0 = a00 * a00 + a02 * a02 + a10 * a10 + a12 * a12;
        float q1 = a01 * a01 + a03 * a03 + a11 * a11 + a13 * a13;
        float mx0 = fmaxf(fmaxf(a00, a02), fmaxf(a10, a12));
        float mx1 = fmaxf(fmaxf(a01, a03), fmaxf(a11, a13));
        float mn0 = fminf(fminf(a00, a02), fminf(a10, a12));
        float mn1 = fminf(fminf(a01, a03), fminf(a11, a13));
        s0 = redg_sum(s0); s1 = redg_sum(s1);
        q0 = redg_sum(q0); q1 = redg_sum(q1);
        mx0 = redg_max(mx0); mx1 = redg_max(mx1);
        mn0 = redg_min(mn0); mn1 = redg_min(mn1);
        if (lane < 4) {
            int col = nw * 64 + nt * 8 + cq;
            *(float2*)(g_max2 + obase + col) = make_float2(mx0, mx1);
            *(float2*)(g_min2 + obase + col) = make_float2(mn0, mn1);
            redS[mw * 128 + col]     = s0;
            redS[mw * 128 + col + 1] = s1;
            redQ[mw * 128 + col]     = q0;
            redQ[mw * 128 + col + 1] = q1;
        }
    }
    __syncthreads();
    {
        int which = tid >> 7, c = tid & 127;
        const float* src = which ? redQ : redS;
        float s = src[c] + src[128 + c] + src[256 + c] + src[384 + c];
        g_part2[(size_t)which * NB2T * C2 + (size_t)blockIdx.x * C2 + c] = s;
    }
}

// ---------------------------------------------------------------------------
// Stats finalize
// ---------------------------------------------------------------------------
__global__ void stats_kernel(int layer, const float* __restrict__ gamma,
                             const float* __restrict__ beta) {
    const float* part; int nb, C; float* scale; float* shift;
    if (layer == 0)      { part = g_part0; nb = NB0T; C = C0;  scale = g_scale0; shift = g_shift0; }
    else if (layer == 1) { part = g_part1; nb = NB1T; C = C1O; scale = g_scale1; shift = g_shift1; }
    else                 { part = g_part2; nb = NB2T; C = C2;  scale = g_scale2; shift = g_shift2; }

    __shared__ float shs[256], shq[256];
    int c = blockIdx.x;
    int tid = threadIdx.x;
    float s = 0.0f, q = 0.0f;
    for (int i = tid; i < nb; i += 256) {
        s += part[(size_t)i * C + c];
        q += part[(size_t)(nb + i) * C + c];
    }
    shs[tid] = s; shq[tid] = q;
    __syncthreads();
    for (int off = 128; off > 0; off >>= 1) {
        if (tid < off) { shs[tid] += shs[tid + off]; shq[tid] += shq[tid + off]; }
        __syncthreads();
    }
    if (tid == 0) {
        float mean = shs[0] / CNT_;
        float var  = shq[0] / CNT_ - mean * mean;
        float sc   = gamma[c] * rsqrtf(var + EPS_);
        scale[c] = sc;
        shift[c] = beta[c] - mean * sc;
    }
}

// ---------------------------------------------------------------------------
// Final output
// ---------------------------------------------------------------------------
__global__ void final_kernel(float* __restrict__ out) {
    int o = blockIdx.x * 256 + threadIdx.x;
    if (o >= B_ * C2 * N2_) return;
    int n2 = o & (N2_ - 1);
    int c  = (o >> 10) & (C2 - 1);
    int b  = o >> 17;
    float sc = g_scale2[c], sh = g_shift2[c];
    size_t mi = (size_t)(b * N2_ + n2) * C2 + c;
    float v = (sc >= 0.0f) ? g_max2[mi] : g_min2[mi];
    out[o] = fmaxf(0.0f, fmaf(sc, v, sh));
}

// ---------------------------------------------------------------------------
// Launcher
// ---------------------------------------------------------------------------
extern "C" void kernel_launch(void* const* d_in, const int* in_sizes, int n_in,
                              void* d_out, int out_size) {
    const float* in_xyz     = (const float*)d_in[0];
    const float* out_xyz    = (const float*)d_in[1];
    const float* in_feature = (const float*)d_in[2];
    const int*   nbr        = (const int*)  d_in[3];
    const float* W0 = (const float*)d_in[4];
    const float* g0 = (const float*)d_in[5];
    const float* b0 = (const float*)d_in[6];
    const float* W1 = (const float*)d_in[7];
    const float* g1 = (const float*)d_in[8];
    const float* b1 = (const float*)d_in[9];
    const float* W2 = (const float*)d_in[10];
    const float* g2 = (const float*)d_in[11];
    const float* b2 = (const float*)d_in[12];
    float* out = (float*)d_out;

    cudaFuncSetAttribute(gemm0t_kernel, cudaFuncAttributeMaxDynamicSharedMemorySize, S0_SMEM);
    cudaFuncSetAttribute(gemm1t_kernel, cudaFuncAttributeMaxDynamicSharedMemorySize, T1_SMEM);
    cudaFuncSetAttribute(gemm2t_kernel, cudaFuncAttributeMaxDynamicSharedMemorySize, T2_SMEM);

    fused_pre_kernel<<<dim3(N1_ / 32 + 1, B_), dim3(32, 8)>>>(in_feature, in_xyz, out_xyz);

    gemm0t_kernel<<<NB0T, 256, S0_SMEM>>>(nbr, W0);
    stats_kernel<<<C0, 256>>>(0, g0, b0);

    gemm1t_kernel<<<NB1T, 256, T1_SMEM>>>(W1);
    stats_kernel<<<C1O, 256>>>(1, g1, b1);

    gemm2t_kernel<<<NB2T, 256, T2_SMEM>>>(W2);
    stats_kernel<<<C2, 256>>>(2, g2, b2);

    final_kernel<<<(B_ * C2 * N2_ + 255) / 256, 256>>>(out);
}

// round 14
// speedup vs baseline: 3.0926x; 1.0001x over previous
#include <cuda_runtime.h>
#include <cuda_bf16.h>
#include <math.h>
#include <cstdint>

// ---------------------------------------------------------------------------
// Problem constants
// ---------------------------------------------------------------------------
#define B_    16
#define N1_   4096
#define N2_   1024
#define KNB   32
#define CIN0  67
#define CPAD  72              // padded to 288B rows (9 aligned 32B sectors)
#define C0    64
#define C1O   64
#define C2    128
#define M_    (B_ * N2_ * KNB)     // 524288
#define NB0T  (M_ / 256)           // 2048
#define NB1T  (M_ / 256)           // 2048
#define NB2T  (M_ / 128)           // 4096
#define CNT_  524288.0f
#define EPS_  1e-5f

// ---------------------------------------------------------------------------
// mma.sync / ldmatrix helpers (baseline PTX, works on compute_103)
// ---------------------------------------------------------------------------
__device__ __forceinline__ void mma_bf16(float* d, const uint32_t* a, const uint32_t* b) {
    asm volatile(
        "mma.sync.aligned.m16n8k16.row.col.f32.bf16.bf16.f32 "
        "{%0,%1,%2,%3}, {%4,%5,%6,%7}, {%8,%9}, {%0,%1,%2,%3};"
        : "+f"(d[0]), "+f"(d[1]), "+f"(d[2]), "+f"(d[3])
        : "r"(a[0]), "r"(a[1]), "r"(a[2]), "r"(a[3]), "r"(b[0]), "r"(b[1]));
}
__device__ __forceinline__ void ldsm_x4(uint32_t* r, uint32_t addr) {
    asm volatile("ldmatrix.sync.aligned.m8n8.x4.shared.b16 {%0,%1,%2,%3}, [%4];"
        : "=r"(r[0]), "=r"(r[1]), "=r"(r[2]), "=r"(r[3]) : "r"(addr));
}
// swizzled smem address for bf16 tiles with 128-byte rows (64 bf16/row)
__device__ __forceinline__ uint32_t sw_off(uint32_t base32, int row, int col) {
    uint32_t byte = (uint32_t)(row * 128 + col * 2);
    byte ^= (byte >> 3) & 0x70;
    return base32 + byte;
}
#define SMEM_SWIZZLE_128B(b) ((b) ^ (((b) >> 3) & 0x70))

// bf16 hi/lo split of two fp32 values, packed as bf16x2 words
__device__ __forceinline__ void split2(float a, float b, uint32_t& hi, uint32_t& lo) {
    __nv_bfloat16 ha = __float2bfloat16(a), hb = __float2bfloat16(b);
    __nv_bfloat16 la = __float2bfloat16(a - __bfloat162float(ha));
    __nv_bfloat16 lb = __float2bfloat16(b - __bfloat162float(hb));
    hi = (uint32_t)__bfloat16_as_ushort(ha) | ((uint32_t)__bfloat16_as_ushort(hb) << 16);
    lo = (uint32_t)__bfloat16_as_ushort(la) | ((uint32_t)__bfloat16_as_ushort(lb) << 16);
}

// butterfly reductions over the g-lanes (lane bits 2..4)
__device__ __forceinline__ float redg_sum(float v) {
    v += __shfl_xor_sync(0xffffffffu, v, 4);
    v += __shfl_xor_sync(0xffffffffu, v, 8);
    v += __shfl_xor_sync(0xffffffffu, v, 16);
    return v;
}
__device__ __forceinline__ float redg_max(float v) {
    v = fmaxf(v, __shfl_xor_sync(0xffffffffu, v, 4));
    v = fmaxf(v, __shfl_xor_sync(0xffffffffu, v, 8));
    v = fmaxf(v, __shfl_xor_sync(0xffffffffu, v, 16));
    return v;
}
__device__ __forceinline__ float redg_min(float v) {
    v = fminf(v, __shfl_xor_sync(0xffffffffu, v, 4));
    v = fminf(v, __shfl_xor_sync(0xffffffffu, v, 8));
    v = fminf(v, __shfl_xor_sync(0xffffffffu, v, 16));
    return v;
}

// ---------------------------------------------------------------------------
// Scratch
// ---------------------------------------------------------------------------
__device__ float g_xallT[(size_t)B_ * N1_ * CPAD];
__device__ float g_oxyz [B_ * N2_ * 4];
__device__ float g_y0[(size_t)M_ * C0];
__device__ float g_y1[(size_t)M_ * C1O];
__device__ float g_part0[2 * NB0T * C0];
__device__ float g_part1[2 * NB1T * C1O];
__device__ float g_part2[2 * NB2T * C2];
__device__ float g_scale0[C0],  g_shift0[C0];
__device__ float g_scale1[C1O], g_shift1[C1O];
__device__ float g_scale2[C2],  g_shift2[C2];
__device__ float g_max2[B_ * N2_ * C2];
__device__ float g_min2[B_ * N2_ * C2];

// ---------------------------------------------------------------------------
// Fused pre: transpose feat+xyz -> [B][N1][72], plus oxyz pack
// ---------------------------------------------------------------------------
__global__ void fused_pre_kernel(const float* __restrict__ in_feature,
                                 const float* __restrict__ in_xyz,
                                 const float* __restrict__ out_xyz) {
    int b  = blockIdx.y;
    int tx = threadIdx.x;
    int ty = threadIdx.y;
    int tid = ty * 32 + tx;

    if (blockIdx.x == N1_ / 32) {
        for (int n2 = tid; n2 < N2_; n2 += 256) {
            int i = b * N2_ + n2;
            g_oxyz[i * 4 + 0] = out_xyz[(b * 3 + 0) * N2_ + n2];
            g_oxyz[i * 4 + 1] = out_xyz[(b * 3 + 1) * N2_ + n2];
            g_oxyz[i * 4 + 2] = out_xyz[(b * 3 + 2) * N2_ + n2];
            g_oxyz[i * 4 + 3] = 0.0f;
        }
        return;
    }

    __shared__ float tile[CPAD][33];
    int n0 = blockIdx.x * 32;
    for (int c = ty; c < CPAD; c += 8) {
        float v;
        if (c < 64)      v = in_feature[((size_t)b * 64 + c) * N1_ + n0 + tx];
        else if (c < 67) v = in_xyz[((size_t)b * 3 + (c - 64)) * N1_ + n0 + tx];
        else             v = 0.0f;
        tile[c][tx] = v;
    }
    __syncthreads();
    for (int e = tid; e < 32 * CPAD; e += 256) {
        int nl = e / CPAD;
        int c  = e % CPAD;
        g_xallT[((size_t)(b * N1_ + n0 + nl)) * CPAD + c] = tile[c][nl];
    }
}

// ---------------------------------------------------------------------------
// GEMM0: gather -> y0 = X(67ch) @ W0^T.  256-row tiles, 8 warps x 32 rows.
// A fragments loaded DIRECTLY from gathered global rows (no X smem).
// feature 64ch via bf16 split MMA; xyz 3ch via exact fp32 FFMA on fragments.
// smem: Wxyz 1K | Whi 8K | Wlo 8K | red 4K = 21504 B
// ---------------------------------------------------------------------------
#define S0_WXYZ  0
#define S0_WHI   1024
#define S0_WLO   9216
#define S0_RED   17408
#define S0_SMEM  21504

__global__ __launch_bounds__(256, 2) void gemm0t_kernel(const int* __restrict__ nbr,
                                                        const float* __restrict__ W0) {
    extern __shared__ char smc[];
    float* Wxyz = (float*)(smc + S0_WXYZ);   // [3][64]
    int tid = threadIdx.x;
    int wid = tid >> 5, lane = tid & 31;

    // W0 feature part [64 cout][64 cin] -> Whi/Wlo swizzled
    for (int e = tid; e < 64 * 64; e += 256) {
        int n = e >> 6, k = e & 63;
        float wv = W0[n * CIN0 + k];
        __nv_bfloat16 h = __float2bfloat16(wv);
        __nv_bfloat16 l = __float2bfloat16(wv - __bfloat162float(h));
        uint32_t byte = (uint32_t)(n * 128 + k * 2);
        uint32_t sw = SMEM_SWIZZLE_128B(byte);
        *(__nv_bfloat16*)(smc + S0_WHI + sw) = h;
        *(__nv_bfloat16*)(smc + S0_WLO + sw) = l;
    }
    if (tid < 192) {
        int c = tid >> 6, n = tid & 63;
        Wxyz[c * 64 + n] = W0[n * CIN0 + 64 + c];
    }

    int g  = lane >> 2;
    int q2 = (lane & 3) * 2;
    int rbase = wid * 32;
    int row0 = blockIdx.x * 256;
    int bb   = row0 >> 15;
    int n2   = ((row0 + rbase) >> 5) & (N2_ - 1);

    // 4 gathered row pointers for this thread (rows g, g+8, g+16, g+24)
    const float* rp[4];
#pragma unroll
    for (int i = 0; i < 4; i++) {
        int idx = nbr[row0 + rbase + g + 8 * i];
        rp[i] = g_xallT + (size_t)(bb * N1_ + idx) * CPAD;
    }
    // xyz for the 4 rows (exact fp32 path)
    float xr[2][2][3];
    {
        const float4 oz = *(const float4*)(g_oxyz + (size_t)(bb * N2_ + n2) * 4);
#pragma unroll
        for (int i = 0; i < 4; i++) {
            float4 p = *(const float4*)(rp[i] + 64);
            xr[i >> 1][i & 1][0] = p.x - oz.x;
            xr[i >> 1][i & 1][1] = p.y - oz.y;
            xr[i >> 1][i & 1][2] = p.z - oz.z;
        }
    }
    __syncthreads();   // W smem ready

    uint32_t whi32 = (uint32_t)__cvta_generic_to_shared(smc + S0_WHI);
    uint32_t wlo32 = (uint32_t)__cvta_generic_to_shared(smc + S0_WLO);
    int rowB7  = (lane & 7) + (((lane >> 4) & 1) << 3);
    int colBof = ((lane >> 3) & 1) << 3;

    float acc[2][8][4];
#pragma unroll
    for (int mt = 0; mt < 2; mt++)
#pragma unroll
        for (int n = 0; n < 8; n++)
#pragma unroll
            for (int j = 0; j < 4; j++) acc[mt][n][j] = 0.0f;

#pragma unroll
    for (int c = 0; c < 4; c++) {
        int kk = c * 16;
        // direct fragment loads (raw values, no BN for layer 0)
        uint32_t ahi[2][4], alo[2][4];
#pragma unroll
        for (int mt = 0; mt < 2; mt++) {
            float2 v0 = *(const float2*)(rp[2 * mt]     + kk + q2);
            float2 v1 = *(const float2*)(rp[2 * mt + 1] + kk + q2);
            float2 v2 = *(const float2*)(rp[2 * mt]     + kk + q2 + 8);
            float2 v3 = *(const float2*)(rp[2 * mt + 1] + kk + q2 + 8);
            split2(v0.x, v0.y, ahi[mt][0], alo[mt][0]);
            split2(v1.x, v1.y, ahi[mt][1], alo[mt][1]);
            split2(v2.x, v2.y, ahi[mt][2], alo[mt][2]);
            split2(v3.x, v3.y, ahi[mt][3], alo[mt][3]);
        }
#pragma unroll
        for (int ntp = 0; ntp < 4; ntp++) {
            uint32_t bh[4], bl[4];
            int rb = ntp * 16 + rowB7;
            ldsm_x4(bh, sw_off(whi32, rb, kk + colBof));
            ldsm_x4(bl, sw_off(wlo32, rb, kk + colBof));
#pragma unroll
            for (int mt = 0; mt < 2; mt++) {
                mma_bf16(acc[mt][2 * ntp],     ahi[mt], bh);
                mma_bf16(acc[mt][2 * ntp],     ahi[mt], bl);
                mma_bf16(acc[mt][2 * ntp],     alo[mt], bh);
                mma_bf16(acc[mt][2 * ntp + 1], ahi[mt], bh + 2);
                mma_bf16(acc[mt][2 * ntp + 1], ahi[mt], bl + 2);
                mma_bf16(acc[mt][2 * ntp + 1], alo[mt], bh + 2);
            }
        }
    }

    // exact fp32 xyz contribution on fragments
#pragma unroll
    for (int nt = 0; nt < 8; nt++) {
        int c = nt * 8 + q2;
#pragma unroll
        for (int ch = 0; ch < 3; ch++) {
            float w0 = Wxyz[ch * 64 + c], w1 = Wxyz[ch * 64 + c + 1];
#pragma unroll
            for (int mt = 0; mt < 2; mt++) {
                acc[mt][nt][0] = fmaf(xr[mt][0][ch], w0, acc[mt][nt][0]);
                acc[mt][nt][1] = fmaf(xr[mt][0][ch], w1, acc[mt][nt][1]);
                acc[mt][nt][2] = fmaf(xr[mt][1][ch], w0, acc[mt][nt][2]);
                acc[mt][nt][3] = fmaf(xr[mt][1][ch], w1, acc[mt][nt][3]);
            }
        }
    }

    // direct global write of y0
    {
        float* dst = g_y0 + (size_t)blockIdx.x * 256 * 64;
#pragma unroll
        for (int mt = 0; mt < 2; mt++) {
            int r0 = rbase + mt * 16 + g;
#pragma unroll
            for (int nt = 0; nt < 8; nt++) {
                int c = nt * 8 + q2;
                *(float2*)(dst + (size_t)r0 * 64 + c)       = make_float2(acc[mt][nt][0], acc[mt][nt][1]);
                *(float2*)(dst + (size_t)(r0 + 8) * 64 + c) = make_float2(acc[mt][nt][2], acc[mt][nt][3]);
            }
        }
    }

    // stats partials via butterfly
    float* redS = (float*)(smc + S0_RED);  // [8][64]
    float* redQ = redS + 512;
#pragma unroll
    for (int nt = 0; nt < 8; nt++) {
        float a00 = acc[0][nt][0], a01 = acc[0][nt][1], a02 = acc[0][nt][2], a03 = acc[0][nt][3];
        float a10 = acc[1][nt][0], a11 = acc[1][nt][1], a12 = acc[1][nt][2], a13 = acc[1][nt][3];
        float s0 = a00 + a02 + a10 + a12;
        float s1 = a01 + a03 + a11 + a13;
        float q0 = a00 * a00 + a02 * a02 + a10 * a10 + a12 * a12;
        float q1 = a01 * a01 + a03 * a03 + a11 * a11 + a13 * a13;
        s0 = redg_sum(s0); s1 = redg_sum(s1);
        q0 = redg_sum(q0); q1 = redg_sum(q1);
        if (lane < 4) {
            redS[wid * 64 + nt * 8 + q2]     = s0;
            redS[wid * 64 + nt * 8 + q2 + 1] = s1;
            redQ[wid * 64 + nt * 8 + q2]     = q0;
            redQ[wid * 64 + nt * 8 + q2 + 1] = q1;
        }
    }
    __syncthreads();
    if (tid < 128) {
        int which = tid >> 6, c = tid & 63;
        const float* src = which ? redQ : redS;
        float s = 0.0f;
#pragma unroll
        for (int w = 0; w < 8; w++) s += src[w * 64 + c];
        g_part0[(size_t)which * NB0T * C0 + (size_t)blockIdx.x * C0 + c] = s;
    }
}

// ---------------------------------------------------------------------------
// GEMM1: y1 = relu(bn0(y0)) @ W1^T.  256-row tiles, direct-A, double-buffered.
// smem: scb 256 | shb 256 | Whi 8K | Wlo 8K | red 4K = 21504 B
// ---------------------------------------------------------------------------
#define T1_SCB  0
#define T1_SHB  256
#define T1_WHI  1024
#define T1_WLO  9216
#define T1_RED  17408
#define T1_SMEM 21504

__global__ __launch_bounds__(256, 2) void gemm1t_kernel(const float* __restrict__ W1) {
    extern __shared__ char smc[];
    float* scb = (float*)(smc + T1_SCB);
    float* shb = (float*)(smc + T1_SHB);
    int tid = threadIdx.x;
    int wid = tid >> 5, lane = tid & 31;

    if (tid < 64) { scb[tid] = g_scale0[tid]; shb[tid] = g_shift0[tid]; }

    for (int e = tid; e < 64 * 64; e += 256) {
        int n = e >> 6, k = e & 63;
        float wv = W1[e];
        __nv_bfloat16 h = __float2bfloat16(wv);
        __nv_bfloat16 l = __float2bfloat16(wv - __bfloat162float(h));
        uint32_t byte = (uint32_t)(n * 128 + k * 2);
        uint32_t sw = SMEM_SWIZZLE_128B(byte);
        *(__nv_bfloat16*)(smc + T1_WHI + sw) = h;
        *(__nv_bfloat16*)(smc + T1_WLO + sw) = l;
    }

    int g  = lane >> 2;
    int q2 = (lane & 3) * 2;
    int rbase = wid * 32;
    const float* yb = g_y0 + (size_t)blockIdx.x * 256 * 64;
    const float* rp[4];
#pragma unroll
    for (int i = 0; i < 4; i++) rp[i] = yb + (size_t)(rbase + g + 8 * i) * 64;

    __syncthreads();   // W + scb ready

    uint32_t whi32 = (uint32_t)__cvta_generic_to_shared(smc + T1_WHI);
    uint32_t wlo32 = (uint32_t)__cvta_generic_to_shared(smc + T1_WLO);
    int rowB7  = (lane & 7) + (((lane >> 4) & 1) << 3);
    int colBof = ((lane >> 3) & 1) << 3;

    float acc[2][8][4];
#pragma unroll
    for (int mt = 0; mt < 2; mt++)
#pragma unroll
        for (int n = 0; n < 8; n++)
#pragma unroll
            for (int j = 0; j < 4; j++) acc[mt][n][j] = 0.0f;

    float2 buf[2][2][4];
    // prefetch chunk 0
#pragma unroll
    for (int mt = 0; mt < 2; mt++) {
        buf[0][mt][0] = *(const float2*)(rp[2 * mt]     + q2);
        buf[0][mt][1] = *(const float2*)(rp[2 * mt + 1] + q2);
        buf[0][mt][2] = *(const float2*)(rp[2 * mt]     + q2 + 8);
        buf[0][mt][3] = *(const float2*)(rp[2 * mt + 1] + q2 + 8);
    }

#pragma unroll
    for (int c = 0; c < 4; c++) {
        int kk = c * 16;
        if (c < 3) {
            int kn = kk + 16;
#pragma unroll
            for (int mt = 0; mt < 2; mt++) {
                buf[(c + 1) & 1][mt][0] = *(const float2*)(rp[2 * mt]     + kn + q2);
                buf[(c + 1) & 1][mt][1] = *(const float2*)(rp[2 * mt + 1] + kn + q2);
                buf[(c + 1) & 1][mt][2] = *(const float2*)(rp[2 * mt]     + kn + q2 + 8);
                buf[(c + 1) & 1][mt][3] = *(const float2*)(rp[2 * mt + 1] + kn + q2 + 8);
            }
        }
        // BN + ReLU + split in registers
        float2 s0 = *(const float2*)(scb + kk + q2);
        float2 h0 = *(const float2*)(shb + kk + q2);
        float2 s2 = *(const float2*)(scb + kk + q2 + 8);
        float2 h2 = *(const float2*)(shb + kk + q2 + 8);
        uint32_t ahi[2][4], alo[2][4];
#pragma unroll
        for (int mt = 0; mt < 2; mt++) {
            float2 v0 = buf[c & 1][mt][0];
            float2 v1 = buf[c & 1][mt][1];
            float2 v2 = buf[c & 1][mt][2];
            float2 v3 = buf[c & 1][mt][3];
            float x00 = fmaxf(0.f, fmaf(v0.x, s0.x, h0.x));
            float x01 = fmaxf(0.f, fmaf(v0.y, s0.y, h0.y));
            float x10 = fmaxf(0.f, fmaf(v1.x, s0.x, h0.x));
            float x11 = fmaxf(0.f, fmaf(v1.y, s0.y, h0.y));
            float x20 = fmaxf(0.f, fmaf(v2.x, s2.x, h2.x));
            float x21 = fmaxf(0.f, fmaf(v2.y, s2.y, h2.y));
            float x30 = fmaxf(0.f, fmaf(v3.x, s2.x, h2.x));
            float x31 = fmaxf(0.f, fmaf(v3.y, s2.y, h2.y));
            split2(x00, x01, ahi[mt][0], alo[mt][0]);
            split2(x10, x11, ahi[mt][1], alo[mt][1]);
            split2(x20, x21, ahi[mt][2], alo[mt][2]);
            split2(x30, x31, ahi[mt][3], alo[mt][3]);
        }
#pragma unroll
        for (int ntp = 0; ntp < 4; ntp++) {
            uint32_t bh[4], bl[4];
            int rb = ntp * 16 + rowB7;
            ldsm_x4(bh, sw_off(whi32, rb, kk + colBof));
            ldsm_x4(bl, sw_off(wlo32, rb, kk + colBof));
#pragma unroll
            for (int mt = 0; mt < 2; mt++) {
                mma_bf16(acc[mt][2 * ntp],     ahi[mt], bh);
                mma_bf16(acc[mt][2 * ntp],     ahi[mt], bl);
                mma_bf16(acc[mt][2 * ntp],     alo[mt], bh);
                mma_bf16(acc[mt][2 * ntp + 1], ahi[mt], bh + 2);
                mma_bf16(acc[mt][2 * ntp + 1], ahi[mt], bl + 2);
                mma_bf16(acc[mt][2 * ntp + 1], alo[mt], bh + 2);
            }
        }
    }

    // direct global write of y1
    {
        float* dst = g_y1 + (size_t)blockIdx.x * 256 * 64;
#pragma unroll
        for (int mt = 0; mt < 2; mt++) {
            int r0 = rbase + mt * 16 + g;
#pragma unroll
            for (int nt = 0; nt < 8; nt++) {
                int c = nt * 8 + q2;
                *(float2*)(dst + (size_t)r0 * 64 + c)       = make_float2(acc[mt][nt][0], acc[mt][nt][1]);
                *(float2*)(dst + (size_t)(r0 + 8) * 64 + c) = make_float2(acc[mt][nt][2], acc[mt][nt][3]);
            }
        }
    }

    // stats partials via butterfly
    float* redS = (float*)(smc + T1_RED);
    float* redQ = redS + 512;
#pragma unroll
    for (int nt = 0; nt < 8; nt++) {
        float a00 = acc[0][nt][0], a01 = acc[0][nt][1], a02 = acc[0][nt][2], a03 = acc[0][nt][3];
        float a10 = acc[1][nt][0], a11 = acc[1][nt][1], a12 = acc[1][nt][2], a13 = acc[1][nt][3];
        float s0 = a00 + a02 + a10 + a12;
        float s1 = a01 + a03 + a11 + a13;
        float q0 = a00 * a00 + a02 * a02 + a10 * a10 + a12 * a12;
        float q1 = a01 * a01 + a03 * a03 + a11 * a11 + a13 * a13;
        s0 = redg_sum(s0); s1 = redg_sum(s1);
        q0 = redg_sum(q0); q1 = redg_sum(q1);
        if (lane < 4) {
            redS[wid * 64 + nt * 8 + q2]     = s0;
            redS[wid * 64 + nt * 8 + q2 + 1] = s1;
            redQ[wid * 64 + nt * 8 + q2]     = q0;
            redQ[wid * 64 + nt * 8 + q2 + 1] = q1;
        }
    }
    __syncthreads();
    if (tid < 128) {
        int which = tid >> 6, c = tid & 63;
        const float* src = which ? redQ : redS;
        float s = 0.0f;
#pragma unroll
        for (int w = 0; w < 8; w++) s += src[w * 64 + c];
        g_part1[(size_t)which * NB1T * C1O + (size_t)blockIdx.x * C1O + c] = s;
    }
}

// ---------------------------------------------------------------------------
// GEMM2: y2 = relu(bn1(y1)) @ W2^T, N=128, 128-row tiles, direct-A.
// Epilogue register-resident: shuffle max/min per K-group + stats.
// smem: scb 256 | shb 256 | Whi 16K | Wlo 16K | red 4K = 37888 B
// ---------------------------------------------------------------------------
#define T2_SCB  0
#define T2_SHB  256
#define T2_WHI  1024
#define T2_WLO  17408
#define T2_RED  33792
#define T2_SMEM 37888

__global__ __launch_bounds__(256, 2) void gemm2t_kernel(const float* __restrict__ W2) {
    extern __shared__ char smc[];
    float* scb = (float*)(smc + T2_SCB);
    float* shb = (float*)(smc + T2_SHB);
    int tid = threadIdx.x;
    int wid = tid >> 5, lane = tid & 31;

    if (tid < 64) { scb[tid] = g_scale1[tid]; shb[tid] = g_shift1[tid]; }

    for (int e = tid; e < 128 * 64; e += 256) {
        int n = e >> 6, k = e & 63;
        float wv = W2[e];
        __nv_bfloat16 h = __float2bfloat16(wv);
        __nv_bfloat16 l = __float2bfloat16(wv - __bfloat162float(h));
        uint32_t byte = (uint32_t)(n * 128 + k * 2);
        uint32_t sw = SMEM_SWIZZLE_128B(byte);
        *(__nv_bfloat16*)(smc + T2_WHI + sw) = h;
        *(__nv_bfloat16*)(smc + T2_WLO + sw) = l;
    }

    // 8 warps = 4 (M) x 2 (N): warp rows mw*32..+31 (one K-group), cols nw*64..+63
    int mw = wid & 3, nw = wid >> 2;
    int g  = lane >> 2;
    int q2 = (lane & 3) * 2;
    int rbase = mw * 32;
    const float* yb = g_y1 + (size_t)blockIdx.x * 128 * 64;
    const float* rp[4];
#pragma unroll
    for (int i = 0; i < 4; i++) rp[i] = yb + (size_t)(rbase + g + 8 * i) * 64;

    __syncthreads();

    uint32_t whi32 = (uint32_t)__cvta_generic_to_shared(smc + T2_WHI);
    uint32_t wlo32 = (uint32_t)__cvta_generic_to_shared(smc + T2_WLO);
    int rowB7  = (lane & 7) + (((lane >> 4) & 1) << 3);
    int colBof = ((lane >> 3) & 1) << 3;

    float acc[2][8][4];
#pragma unroll
    for (int mt = 0; mt < 2; mt++)
#pragma unroll
        for (int n = 0; n < 8; n++)
#pragma unroll
            for (int j = 0; j < 4; j++) acc[mt][n][j] = 0.0f;

    float2 buf[2][2][4];
#pragma unroll
    for (int mt = 0; mt < 2; mt++) {
        buf[0][mt][0] = *(const float2*)(rp[2 * mt]     + q2);
        buf[0][mt][1] = *(const float2*)(rp[2 * mt + 1] + q2);
        buf[0][mt][2] = *(const float2*)(rp[2 * mt]     + q2 + 8);
        buf[0][mt][3] = *(const float2*)(rp[2 * mt + 1] + q2 + 8);
    }

#pragma unroll
    for (int c = 0; c < 4; c++) {
        int kk = c * 16;
        if (c < 3) {
            int kn = kk + 16;
#pragma unroll
            for (int mt = 0; mt < 2; mt++) {
                buf[(c + 1) & 1][mt][0] = *(const float2*)(rp[2 * mt]     + kn + q2);
                buf[(c + 1) & 1][mt][1] = *(const float2*)(rp[2 * mt + 1] + kn + q2);
                buf[(c + 1) & 1][mt][2] = *(const float2*)(rp[2 * mt]     + kn + q2 + 8);
                buf[(c + 1) & 1][mt][3] = *(const float2*)(rp[2 * mt + 1] + kn + q2 + 8);
            }
        }
        float2 s0 = *(const float2*)(scb + kk + q2);
        float2 h0 = *(const float2*)(shb + kk + q2);
        float2 s2 = *(const float2*)(scb + kk + q2 + 8);
        float2 h2 = *(const float2*)(shb + kk + q2 + 8);
        uint32_t ahi[2][4], alo[2][4];
#pragma unroll
        for (int mt = 0; mt < 2; mt++) {
            float2 v0 = buf[c & 1][mt][0];
            float2 v1 = buf[c & 1][mt][1];
            float2 v2 = buf[c & 1][mt][2];
            float2 v3 = buf[c & 1][mt][3];
            float x00 = fmaxf(0.f, fmaf(v0.x, s0.x, h0.x));
            float x01 = fmaxf(0.f, fmaf(v0.y, s0.y, h0.y));
            float x10 = fmaxf(0.f, fmaf(v1.x, s0.x, h0.x));
            float x11 = fmaxf(0.f, fmaf(v1.y, s0.y, h0.y));
            float x20 = fmaxf(0.f, fmaf(v2.x, s2.x, h2.x));
            float x21 = fmaxf(0.f, fmaf(v2.y, s2.y, h2.y));
            float x30 = fmaxf(0.f, fmaf(v3.x, s2.x, h2.x));
            float x31 = fmaxf(0.f, fmaf(v3.y, s2.y, h2.y));
            split2(x00, x01, ahi[mt][0], alo[mt][0]);
            split2(x10, x11, ahi[mt][1], alo[mt][1]);
            split2(x20, x21, ahi[mt][2], alo[mt][2]);
            split2(x30, x31, ahi[mt][3], alo[mt][3]);
        }
#pragma unroll
        for (int ntp = 0; ntp < 4; ntp++) {
            uint32_t bh[4], bl[4];
            int rb = nw * 64 + ntp * 16 + rowB7;
            ldsm_x4(bh, sw_off(whi32, rb, kk + colBof));
            ldsm_x4(bl, sw_off(wlo32, rb, kk + colBof));
#pragma unroll
            for (int mt = 0; mt < 2; mt++) {
                mma_bf16(acc[mt][2 * ntp],     ahi[mt], bh);
                mma_bf16(acc[mt][2 * ntp],     ahi[mt], bl);
                mma_bf16(acc[mt][2 * ntp],     alo[mt], bh);
                mma_bf16(acc[mt][2 * ntp + 1], ahi[mt], bh + 2);
                mma_bf16(acc[mt][2 * ntp + 1], ahi[mt], bl + 2);
                mma_bf16(acc[mt][2 * ntp + 1], alo[mt], bh + 2);
            }
        }
    }

    // register-resident epilogue: the warp's 32 rows == one K-group
    int row0 = blockIdx.x * 128;
    int b_   = row0 >> 15;
    int n2g  = ((row0 >> 5) & (N2_ - 1)) + mw;
    float* redS = (float*)(smc + T2_RED);   // [4 mw][128]
    float* redQ = redS + 512;
    size_t obase = (size_t)(b_ * N2_ + n2g) * C2;

#pragma unroll
    for (int nt = 0; nt < 8; nt++) {
        float a00 = acc[0][nt][0], a01 = acc[0][nt][1], a02 = acc[0][nt][2], a03 = acc[0][nt][3];
        float a10 = acc[1][nt][0], a11 = acc[1][nt][1], a12 = acc[1][nt][2], a13 = acc[1][nt][3];
        float s0 = a00 + a02 + a10 + a12;
        float s1 = a01 + a03 + a11 + a13;
        float q0 = a00 * a00 + a02 * a02 + a10 * a10 + a12 * a12;
        float q1 = a01 * a01 + a03 * a03 + a11 * a11 + a13 * a13;
        float mx0 = fmaxf(fmaxf(a00, a02), fmaxf(a10, a12));
        float mx1 = fmaxf(fmaxf(a01, a03), fmaxf(a11, a13));
        float mn0 = fminf(fminf(a00, a02), fminf(a10, a12));
        float mn1 = fminf(fminf(a01, a03), fminf(a11, a13));
        s0 = redg_sum(s0); s1 = redg_sum(s1);
        q0 = redg_sum(q0); q1 = redg_sum(q1);
        mx0 = redg_max(mx0); mx1 = redg_max(mx1);
        mn0 = redg_min(mn0); mn1 = redg_min(mn1);
        if (lane < 4) {
            int col = nw * 64 + nt * 8 + q2;
            *(float2*)(g_max2 + obase + col) = make_float2(mx0, mx1);
            *(float2*)(g_min2 + obase + col) = make_float2(mn0, mn1);
            redS[mw * 128 + col]     = s0;
            redS[mw * 128 + col + 1] = s1;
            redQ[mw * 128 + col]     = q0;
            redQ[mw * 128 + col + 1] = q1;
        }
    }
    __syncthreads();
    {
        int which = tid >> 7, c = tid & 127;
        const float* src = which ? redQ : redS;
        float s = src[c] + src[128 + c] + src[256 + c] + src[384 + c];
        g_part2[(size_t)which * NB2T * C2 + (size_t)blockIdx.x * C2 + c] = s;
    }
}

// ---------------------------------------------------------------------------
// Stats finalize
// ---------------------------------------------------------------------------
__global__ void stats_kernel(int layer, const float* __restrict__ gamma,
                             const float* __restrict__ beta) {
    const float* part; int nb, C; float* scale; float* shift;
    if (layer == 0)      { part = g_part0; nb = NB0T; C = C0;  scale = g_scale0; shift = g_shift0; }
    else if (layer == 1) { part = g_part1; nb = NB1T; C = C1O; scale = g_scale1; shift = g_shift1; }
    else                 { part = g_part2; nb = NB2T; C = C2;  scale = g_scale2; shift = g_shift2; }

    __shared__ float shs[256], shq[256];
    int c = blockIdx.x;
    int tid = threadIdx.x;
    float s = 0.0f, q = 0.0f;
    for (int i = tid; i < nb; i += 256) {
        s += part[(size_t)i * C + c];
        q += part[(size_t)(nb + i) * C + c];
    }
    shs[tid] = s; shq[tid] = q;
    __syncthreads();
    for (int off = 128; off > 0; off >>= 1) {
        if (tid < off) { shs[tid] += shs[tid + off]; shq[tid] += shq[tid + off]; }
        __syncthreads();
    }
    if (tid == 0) {
        float mean = shs[0] / CNT_;
        float var  = shq[0] / CNT_ - mean * mean;
        float sc   = gamma[c] * rsqrtf(var + EPS_);
        scale[c] = sc;
        shift[c] = beta[c] - mean * sc;
    }
}

// ---------------------------------------------------------------------------
// Final output
// ---------------------------------------------------------------------------
__global__ void final_kernel(float* __restrict__ out) {
    int o = blockIdx.x * 256 + threadIdx.x;
    if (o >= B_ * C2 * N2_) return;
    int n2 = o & (N2_ - 1);
    int c  = (o >> 10) & (C2 - 1);
    int b  = o >> 17;
    float sc = g_scale2[c], sh = g_shift2[c];
    size_t mi = (size_t)(b * N2_ + n2) * C2 + c;
    float v = (sc >= 0.0f) ? g_max2[mi] : g_min2[mi];
    out[o] = fmaxf(0.0f, fmaf(sc, v, sh));
}

// ---------------------------------------------------------------------------
// Launcher
// ---------------------------------------------------------------------------
extern "C" void kernel_launch(void* const* d_in, const int* in_sizes, int n_in,
                              void* d_out, int out_size) {
    const float* in_xyz     = (const float*)d_in[0];
    const float* out_xyz    = (const float*)d_in[1];
    const float* in_feature = (const float*)d_in[2];
    const int*   nbr        = (const int*)  d_in[3];
    const float* W0 = (const float*)d_in[4];
    const float* g0 = (const float*)d_in[5];
    const float* b0 = (const float*)d_in[6];
    const float* W1 = (const float*)d_in[7];
    const float* g1 = (const float*)d_in[8];
    const float* b1 = (const float*)d_in[9];
    const float* W2 = (const float*)d_in[10];
    const float* g2 = (const float*)d_in[11];
    const float* b2 = (const float*)d_in[12];
    float* out = (float*)d_out;

    cudaFuncSetAttribute(gemm0t_kernel, cudaFuncAttributeMaxDynamicSharedMemorySize, S0_SMEM);
    cudaFuncSetAttribute(gemm1t_kernel, cudaFuncAttributeMaxDynamicSharedMemorySize, T1_SMEM);
    cudaFuncSetAttribute(gemm2t_kernel, cudaFuncAttributeMaxDynamicSharedMemorySize, T2_SMEM);

    // launch order keeps gemm2t at index 5 for the fixed ncu -s 5 -c 1 window
    fused_pre_kernel<<<dim3(N1_ / 32 + 1, B_), dim3(32, 8)>>>(in_feature, in_xyz, out_xyz);

    gemm0t_kernel<<<NB0T, 256, S0_SMEM>>>(nbr, W0);
    stats_kernel<<<C0, 256>>>(0, g0, b0);

    gemm1t_kernel<<<NB1T, 256, T1_SMEM>>>(W1);
    stats_kernel<<<C1O, 256>>>(1, g1, b1);

    gemm2t_kernel<<<NB2T, 256, T2_SMEM>>>(W2);
    stats_kernel<<<C2, 256>>>(2, g2, b2);

    final_kernel<<<(B_ * C2 * N2_ + 255) / 256, 256>>>(out);
}